// round 3
// baseline (speedup 1.0000x reference)
#include <cuda_runtime.h>
#include <cstdint>

#define CN   32
#define HID  256
#define K3   96
#define HH   256
#define WW   256
#define BB   8
#define NPIX (BB*HH*WW)          /* 524288 */
#define NROWS (NPIX/WW)          /* 2048 */
#define ROWS_PER_BLOCK 2
#define SMEM_FLOATS (HID*K3 + CN*HID + HID)   /* 33024 floats -> 132096 B */

/* planar (SoA) ping-pong scratch: [c][pix] */
__device__ float g_p0[(size_t)CN * NPIX];
__device__ float g_p1[(size_t)CN * NPIX];

/* ---------------- packed f32x2 helpers (Blackwell FFMA2 path) ---------------- */
static __device__ __forceinline__ unsigned long long f2fma(unsigned long long a,
                                                           unsigned long long b,
                                                           unsigned long long c) {
    unsigned long long d;
    asm("fma.rn.f32x2 %0, %1, %2, %3;" : "=l"(d) : "l"(a), "l"(b), "l"(c));
    return d;
}
static __device__ __forceinline__ unsigned long long pk2(float a, float b) {
    unsigned long long r;
    asm("mov.b64 %0, {%1, %2};" : "=l"(r) : "f"(a), "f"(b));
    return r;
}
static __device__ __forceinline__ float2 up2(unsigned long long v) {
    float2 r;
    asm("mov.b64 {%0, %1}, %2;" : "=f"(r.x), "=f"(r.y) : "l"(v));
    return r;
}

/* ---------------- JAX threefry2x32 block (20 rounds) ---------------- */
static __device__ __forceinline__ uint2 threefry(uint32_t k0, uint32_t k1,
                                                 uint32_t x0, uint32_t x1) {
    uint32_t ks2 = k0 ^ k1 ^ 0x1BD11BDAu;
    x0 += k0; x1 += k1;
#define TF_R(r) { x0 += x1; x1 = __funnelshift_l(x1, x1, (r)); x1 ^= x0; }
    TF_R(13) TF_R(15) TF_R(26) TF_R(6)   x0 += k1;  x1 += ks2 + 1u;
    TF_R(17) TF_R(29) TF_R(16) TF_R(24)  x0 += ks2; x1 += k0  + 2u;
    TF_R(13) TF_R(15) TF_R(26) TF_R(6)   x0 += k0;  x1 += k1  + 3u;
    TF_R(17) TF_R(29) TF_R(16) TF_R(24)  x0 += k1;  x1 += ks2 + 4u;
    TF_R(13) TF_R(15) TF_R(26) TF_R(6)   x0 += ks2; x1 += k0  + 5u;
#undef TF_R
    return make_uint2(x0, x1);
}

/* ---------------- AoS [pix][32] -> planar [c][pix] transpose ---------------- */
__global__ void __launch_bounds__(256, 4)
aos_to_planar(const float* __restrict__ src, float* __restrict__ dst)
{
    __shared__ float tile[CN][33];
    const int tid = threadIdx.x;
    const int base = blockIdx.x * 32;

    {   /* load 32 pixels x 32 channels, coalesced over channels */
        const int p  = tid >> 3;        /* 0..31 */
        const int cg = tid & 7;         /* 0..7  */
        float4 v = *(const float4*)(src + ((size_t)(base + p)) * CN + cg * 4);
        tile[cg*4 + 0][p] = v.x;
        tile[cg*4 + 1][p] = v.y;
        tile[cg*4 + 2][p] = v.z;
        tile[cg*4 + 3][p] = v.w;
    }
    __syncthreads();
    {   /* store coalesced over pixels */
        const int p = tid & 31;
        const int c0 = tid >> 5;        /* 0..7 */
        #pragma unroll
        for (int i = 0; i < 4; ++i) {
            const int c = c0 + i * 8;
            dst[(size_t)c * NPIX + base + p] = tile[c][p];
        }
    }
}

/* ---------------- fused NCA step (planar in; OUTMODE 0=planar 1=AoS) -------- */
template <int OUTMODE>
__global__ void __launch_bounds__(256, 1)
nca_step(const float* __restrict__ xin, float* __restrict__ xout,
         const float* __restrict__ fc0w, const float* __restrict__ fc0b,
         const float* __restrict__ fc1w, const int* __restrict__ stepsPtr,
         int stepIdx)
{
    const int tid = threadIdx.x;
    const int S = *stepsPtr;
    const int rowBase = blockIdx.x * ROWS_PER_BLOCK;

    if (stepIdx >= S) {                          /* identity pass-through */
        #pragma unroll
        for (int r = 0; r < ROWS_PER_BLOCK; ++r) {
            const int p = (rowBase + r) * WW + tid;
            if (OUTMODE == 0) {
                #pragma unroll
                for (int c = 0; c < CN; ++c)
                    xout[(size_t)c * NPIX + p] = xin[(size_t)c * NPIX + p];
            } else {
                float v[CN];
                #pragma unroll
                for (int c = 0; c < CN; ++c) v[c] = xin[(size_t)c * NPIX + p];
                float4* d = (float4*)(xout + (size_t)p * CN);
                #pragma unroll
                for (int q = 0; q < 8; ++q)
                    d[q] = make_float4(v[4*q], v[4*q+1], v[4*q+2], v[4*q+3]);
            }
        }
        return;
    }

    extern __shared__ float smem[];
    float* sW0 = smem;                 /* [256][96]  row-major fc0_w */
    float* sW1 = sW0 + HID * K3;       /* [32][256]  row-major fc1_w */
    float* sB  = sW1 + CN * HID;       /* [256] */

    {   /* coalesced, conflict-free weight staging */
        const float4* s0 = (const float4*)fc0w;  float4* d0 = (float4*)sW0;
        #pragma unroll
        for (int i = tid; i < HID * K3 / 4; i += 256) d0[i] = s0[i];
        const float4* s1 = (const float4*)fc1w;  float4* d1 = (float4*)sW1;
        #pragma unroll
        for (int i = tid; i < CN * HID / 4; i += 256) d1[i] = s1[i];
        if (tid < HID) sB[tid] = fc0b[tid];
    }
    __syncthreads();

    const uint2 fk = threefry(0u, 42u, 0u, (uint32_t)stepIdx);

    #pragma unroll 1
    for (int r = 0; r < ROWS_PER_BLOCK; ++r) {
        const int row = rowBase + r;             /* row = b*256 + h */
        const int h = row & (HH - 1);
        const int w = tid;
        const int p = row * WW + w;

        const bool hu = (h > 0), hd = (h < HH - 1);
        const bool wl = (w > 0), wr = (w < WW - 1);

        /* ---- perceive (planar, coalesced): y2[0..15]=x, [16..31]=dx, [32..47]=dy ---- */
        unsigned long long y2[48];
        #pragma unroll
        for (int cp = 0; cp < 16; ++cp) {
            float xcv[2], dxv[2], dyv[2];
            #pragma unroll
            for (int i = 0; i < 2; ++i) {
                const float* xc = xin + (size_t)(2*cp + i) * NPIX + p;
                float cc = xc[0];
                float ul = (hu && wl) ? xc[-WW-1] : 0.f;
                float uc =  hu        ? xc[-WW]   : 0.f;
                float ur = (hu && wr) ? xc[-WW+1] : 0.f;
                float cl =  wl        ? xc[-1]    : 0.f;
                float cr =  wr        ? xc[ 1]    : 0.f;
                float bl = (hd && wl) ? xc[ WW-1] : 0.f;
                float bc =  hd        ? xc[ WW]   : 0.f;
                float br = (hd && wr) ? xc[ WW+1] : 0.f;
                xcv[i] = cc;
                dxv[i] = 0.125f * ((bl - ul) + 2.f * (bc - uc) + (br - ur));
                dyv[i] = 0.125f * ((ur - ul) + 2.f * (cr - cl) + (br - bl));
            }
            y2[cp]      = pk2(xcv[0], xcv[1]);
            y2[16 + cp] = pk2(dxv[0], dxv[1]);
            y2[32 + cp] = pk2(dyv[0], dyv[1]);
        }

        /* ---- MLP: h = W0 y + b (pair over k), d = W1 h (pair over o) ---- */
        unsigned long long dacc[CN];
        #pragma unroll
        for (int c = 0; c < CN; ++c) dacc[c] = 0ull;

        #pragma unroll 1
        for (int og = 0; og < HID; og += 8) {
            unsigned long long hp[8];
            #pragma unroll
            for (int t = 0; t < 8; ++t) hp[t] = 0ull;

            const float* w0base = sW0 + og * K3;
            #pragma unroll
            for (int j = 0; j < 24; ++j) {
                #pragma unroll
                for (int t = 0; t < 8; ++t) {     /* 8 independent chains */
                    ulonglong2 wv = *(const ulonglong2*)(w0base + t * K3 + j * 4);
                    hp[t] = f2fma(y2[2*j],     wv.x, hp[t]);
                    hp[t] = f2fma(y2[2*j + 1], wv.y, hp[t]);
                }
            }
            unsigned long long hpair[4];
            #pragma unroll
            for (int q = 0; q < 4; ++q) {
                float2 a = up2(hp[2*q]);
                float2 b = up2(hp[2*q + 1]);
                hpair[q] = pk2(a.x + a.y + sB[og + 2*q],
                               b.x + b.y + sB[og + 2*q + 1]);
            }
            #pragma unroll
            for (int c = 0; c < CN; ++c) {        /* 32 independent chains */
                const float* w1 = sW1 + c * HID + og;
                ulonglong2 wa = *(const ulonglong2*)(w1);
                ulonglong2 wb = *(const ulonglong2*)(w1 + 4);
                dacc[c] = f2fma(hpair[0], wa.x, dacc[c]);
                dacc[c] = f2fma(hpair[1], wa.y, dacc[c]);
                dacc[c] = f2fma(hpair[2], wb.x, dacc[c]);
                dacc[c] = f2fma(hpair[3], wb.y, dacc[c]);
            }
        }

        /* ---- fire mask: JAX threefry (partitionable path), uniform>0.5 ---- */
        const uint32_t j32 = (uint32_t)p;
        uint2 rb = threefry(fk.x, fk.y, 0u, j32);
        uint32_t bits = rb.x ^ rb.y;
        float u = __uint_as_float((bits >> 9) | 0x3f800000u) - 1.0f;
        float m = (u > 0.5f) ? 1.0f : 0.0f;

        /* ---- update + store ---- */
        float outv[CN];
        #pragma unroll
        for (int c = 0; c < CN; ++c) {
            float2 dp = up2(dacc[c]);
            float dsum = dp.x + dp.y;
            float2 xv = up2(y2[c >> 1]);
            float xc = (c & 1) ? xv.y : xv.x;
            float t = xc + dsum * m;
            float sg = __fdividef(1.0f, 1.0f + __expf(-t));
            outv[c] = (c < 3) ? xc : sg;
        }
        if (OUTMODE == 0) {
            #pragma unroll
            for (int c = 0; c < CN; ++c)
                xout[(size_t)c * NPIX + p] = outv[c];
        } else {
            float4* dstp = (float4*)(xout + (size_t)p * CN);
            #pragma unroll
            for (int q = 0; q < 8; ++q)
                dstp[q] = make_float4(outv[4*q], outv[4*q+1], outv[4*q+2], outv[4*q+3]);
        }
    }
}

/* ---------------- launch ---------------- */
extern "C" void kernel_launch(void* const* d_in, const int* in_sizes, int n_in,
                              void* d_out, int out_size)
{
    const float* x    = (const float*)d_in[0];
    const float* fc0w = (const float*)d_in[1];
    const float* fc0b = (const float*)d_in[2];
    const float* fc1w = (const float*)d_in[3];
    const int*   st   = (const int*)d_in[4];
    float* out = (float*)d_out;

    float *p0 = nullptr, *p1 = nullptr;
    cudaGetSymbolAddress((void**)&p0, g_p0);
    cudaGetSymbolAddress((void**)&p1, g_p1);

    const int smemBytes = SMEM_FLOATS * (int)sizeof(float);
    cudaFuncSetAttribute((const void*)nca_step<0>,
                         cudaFuncAttributeMaxDynamicSharedMemorySize, smemBytes);
    cudaFuncSetAttribute((const void*)nca_step<1>,
                         cudaFuncAttributeMaxDynamicSharedMemorySize, smemBytes);

    dim3 blk(256);
    aos_to_planar<<<NPIX / 32, blk>>>(x, p0);
    dim3 grid(NROWS / ROWS_PER_BLOCK);   /* 1024 */
    nca_step<0><<<grid, blk, smemBytes>>>(p0, p1,  fc0w, fc0b, fc1w, st, 0);
    nca_step<1><<<grid, blk, smemBytes>>>(p1, out, fc0w, fc0b, fc1w, st, 1);
}

// round 5
// speedup vs baseline: 1.7750x; 1.7750x over previous
#include <cuda_runtime.h>
#include <cstdint>

#define CN   32
#define HID  256
#define K3   96
#define WW   256
#define NPIX (8*256*256)         /* 524288 */
#define TILE 128
#define NTILES (NPIX/TILE)       /* 4096 */
#define THREADS 256

/* smem strides (in floats) */
#define YS 100                   /* Y row stride: stride%32==4 -> conflict-free A-frag loads */
#define HS 72                    /* H chunk row stride */
#define DS 40                    /* D row stride */

/* smem byte offsets */
#define W0F_B 0                  /* W0 B-fragments: 12kt*32nt*32thr*8B = 98304 */
#define W1F_B 98304              /* W1 B-fragments: 32kt*4nt*32thr*8B = 32768 */
#define H_B   131072             /* H chunk: 128*72*4 = 36864 */
#define Y_B   167936             /* Y: 128*100*4 = 51200 */
#define D_B   Y_B                /* D aliases Y: 128*40*4 = 20480 */
#define C2_B  219136             /* 32 floats */
#define SMEM_BYTES 219264

/* planar (SoA) ping-pong scratch: [c][pix] */
__device__ float g_p0[(size_t)CN * NPIX];
__device__ float g_p1[(size_t)CN * NPIX];

/* ================= helpers ================= */
static __device__ __forceinline__ uint32_t to_tf32(float x) {
    uint32_t r; asm("cvt.rna.tf32.f32 %0, %1;" : "=r"(r) : "f"(x)); return r;
}
static __device__ __forceinline__ void mma8(float& d0, float& d1, float& d2, float& d3,
                                            uint32_t a0, uint32_t a1, uint32_t a2, uint32_t a3,
                                            uint32_t b0, uint32_t b1) {
    asm volatile("mma.sync.aligned.m16n8k8.row.col.f32.tf32.tf32.f32 "
                 "{%0,%1,%2,%3}, {%4,%5,%6,%7}, {%8,%9}, {%0,%1,%2,%3};"
                 : "+f"(d0), "+f"(d1), "+f"(d2), "+f"(d3)
                 : "r"(a0), "r"(a1), "r"(a2), "r"(a3), "r"(b0), "r"(b1));
}

/* ---------------- JAX threefry2x32 (validated R2) ---------------- */
static __device__ __forceinline__ uint2 threefry(uint32_t k0, uint32_t k1,
                                                 uint32_t x0, uint32_t x1) {
    uint32_t ks2 = k0 ^ k1 ^ 0x1BD11BDAu;
    x0 += k0; x1 += k1;
#define TF_R(r) { x0 += x1; x1 = __funnelshift_l(x1, x1, (r)); x1 ^= x0; }
    TF_R(13) TF_R(15) TF_R(26) TF_R(6)   x0 += k1;  x1 += ks2 + 1u;
    TF_R(17) TF_R(29) TF_R(16) TF_R(24)  x0 += ks2; x1 += k0  + 2u;
    TF_R(13) TF_R(15) TF_R(26) TF_R(6)   x0 += k0;  x1 += k1  + 3u;
    TF_R(17) TF_R(29) TF_R(16) TF_R(24)  x0 += k1;  x1 += ks2 + 4u;
    TF_R(13) TF_R(15) TF_R(26) TF_R(6)   x0 += ks2; x1 += k0  + 5u;
#undef TF_R
    return make_uint2(x0, x1);
}

/* ---------------- AoS [pix][32] -> planar [c][pix] ---------------- */
__global__ void __launch_bounds__(256, 4)
aos_to_planar(const float* __restrict__ src, float* __restrict__ dst)
{
    __shared__ float tile[CN][33];
    const int tid = threadIdx.x;
    const int base = blockIdx.x * 32;
    {
        const int p  = tid >> 3;
        const int cg = tid & 7;
        float4 v = *(const float4*)(src + ((size_t)(base + p)) * CN + cg * 4);
        tile[cg*4 + 0][p] = v.x;  tile[cg*4 + 1][p] = v.y;
        tile[cg*4 + 2][p] = v.z;  tile[cg*4 + 3][p] = v.w;
    }
    __syncthreads();
    {
        const int p = tid & 31;
        const int c0 = tid >> 5;
        #pragma unroll
        for (int i = 0; i < 4; ++i) {
            const int c = c0 + i * 8;
            dst[(size_t)c * NPIX + base + p] = tile[c][p];
        }
    }
}

/* ================= fused NCA step on mma.sync tensor cores ================= */
template <int OUTMODE>   /* 0 = planar out, 1 = AoS out (final) */
__global__ void __launch_bounds__(THREADS, 1)
nca_mma(const float* __restrict__ xin, float* __restrict__ xout,
        const float* __restrict__ fc0w, const float* __restrict__ fc0b,
        const float* __restrict__ fc1w, const int* __restrict__ stepsPtr,
        int stepIdx)
{
    extern __shared__ char smb[];
    const int tid  = threadIdx.x;
    const int lane = tid & 31;
    const int warp = tid >> 5;
    const int S = *stepsPtr;
    const int p   = tid & 127;            /* pixel within tile (stencil/epilogue role) */
    const int chb = (tid >> 7) * 16;      /* channel half base */

    if (stepIdx >= S) {                   /* identity pass-through */
        for (int tile = blockIdx.x; tile < NTILES; tile += gridDim.x) {
            const int pg = tile * TILE + p;
            #pragma unroll
            for (int j = 0; j < 16; ++j) {
                int c = chb + j;
                float v = xin[(size_t)c * NPIX + pg];
                if (OUTMODE == 0) xout[(size_t)c * NPIX + pg] = v;
                else              xout[(size_t)pg * CN + c] = v;
            }
        }
        return;
    }

    /* -------- one-time: pre-arrange weight fragments + bias fold -------- */
    uint2* w0f = (uint2*)(smb + W0F_B);   /* [(kt*32+nt)*32+lane] -> (b0,b1) */
    for (int e = tid; e < 12*32*32; e += THREADS) {
        int kt = e >> 10, rem = e & 1023, nt = rem >> 5, t = rem & 31;
        int n = nt*8 + (t >> 2), k = kt*8 + (t & 3);
        uint2 v; v.x = to_tf32(fc0w[n*K3 + k]); v.y = to_tf32(fc0w[n*K3 + k + 4]);
        w0f[e] = v;
    }
    uint2* w1f = (uint2*)(smb + W1F_B);   /* [(kt*4+nt)*32+lane] */
    for (int e = tid; e < 32*4*32; e += THREADS) {
        int kt = e >> 7, rem = e & 127, nt = rem >> 5, t = rem & 31;
        int n = nt*8 + (t >> 2), k = kt*8 + (t & 3);
        uint2 v; v.x = to_tf32(fc1w[n*HID + k]); v.y = to_tf32(fc1w[n*HID + k + 4]);
        w1f[e] = v;
    }
    float* c2 = (float*)(smb + C2_B);
    if (tid < CN) {                        /* c2 = W1 * b (bias folded linearly) */
        float s = 0.f;
        const float* wr = fc1w + tid * HID;
        #pragma unroll 8
        for (int h2 = 0; h2 < HID; ++h2) s += wr[h2] * fc0b[h2];
        c2[tid] = s;
    }
    __syncthreads();

    uint32_t* Ysm = (uint32_t*)(smb + Y_B);
    uint32_t* Hsm = (uint32_t*)(smb + H_B);
    float*    Dsm = (float*)(smb + D_B);

    const uint2 fk = threefry(0u, 42u, 0u, (uint32_t)stepIdx);
    const int g = lane >> 2, tig = lane & 3;
    const int rw = warp * 16;

    for (int tile = blockIdx.x; tile < NTILES; tile += gridDim.x) {
        const int pg = tile * TILE + p;
        const int hrow = (pg >> 8) & 255;
        const int wc = pg & 255;
        const bool hu = (hrow > 0), hd = (hrow < 255);
        const bool wl = (wc > 0),  wr = (wc < 255);

        /* ---- stencil via warp shuffles (3 LDG/channel + edge fixups) ---- */
        float xv[16];
        #pragma unroll
        for (int j = 0; j < 16; ++j) {
            const float* xc = xin + (size_t)(chb + j) * NPIX + pg;
            float uc = hu ? xc[-WW] : 0.f;
            float cc = xc[0];
            float bc = hd ? xc[ WW] : 0.f;
            float ul = __shfl_up_sync(0xffffffffu, uc, 1);
            float cl = __shfl_up_sync(0xffffffffu, cc, 1);
            float bl = __shfl_up_sync(0xffffffffu, bc, 1);
            if (lane == 0) {
                ul = (hu && wl) ? xc[-WW-1] : 0.f;
                cl =  wl        ? xc[-1]    : 0.f;
                bl = (hd && wl) ? xc[ WW-1] : 0.f;
            }
            float ur = __shfl_down_sync(0xffffffffu, uc, 1);
            float cr = __shfl_down_sync(0xffffffffu, cc, 1);
            float br = __shfl_down_sync(0xffffffffu, bc, 1);
            if (lane == 31) {
                ur = (hu && wr) ? xc[-WW+1] : 0.f;
                cr =  wr        ? xc[ 1]    : 0.f;
                br = (hd && wr) ? xc[ WW+1] : 0.f;
            }
            float dx = 0.125f * ((bl - ul) + 2.f * (bc - uc) + (br - ur));
            float dy = 0.125f * ((ur - ul) + 2.f * (cr - cl) + (br - bl));
            xv[j] = cc;
            Ysm[p*YS +      chb + j] = to_tf32(cc);
            Ysm[p*YS + 32 + chb + j] = to_tf32(dx);
            Ysm[p*YS + 64 + chb + j] = to_tf32(dy);
        }
        __syncthreads();                       /* Y visible */

        /* ---- GEMMs on mma.sync; warp owns rows rw..rw+15 ---- */
        float d0[4], d1[4], d2[4], d3[4];
        #pragma unroll
        for (int q = 0; q < 4; ++q) { d0[q]=0.f; d1[q]=0.f; d2[q]=0.f; d3[q]=0.f; }

        #pragma unroll 1
        for (int nc = 0; nc < 4; ++nc) {       /* 64-col H chunks */
            float acc[8][4];
            #pragma unroll
            for (int nt = 0; nt < 8; ++nt)
                #pragma unroll
                for (int q = 0; q < 4; ++q) acc[nt][q] = 0.f;

            /* GEMM1: acc += Y[rw..rw+15][:] * W0^T[:, nc*64..] */
            #pragma unroll
            for (int kt = 0; kt < 12; ++kt) {
                const int col = kt*8 + tig;
                uint32_t a0 = Ysm[(rw+g)*YS + col];
                uint32_t a1 = Ysm[(rw+g+8)*YS + col];
                uint32_t a2 = Ysm[(rw+g)*YS + col + 4];
                uint32_t a3 = Ysm[(rw+g+8)*YS + col + 4];
                const uint2* bf = w0f + (kt*32 + nc*8)*32 + lane;
                #pragma unroll
                for (int nt = 0; nt < 8; ++nt) {
                    uint2 b = bf[nt*32];
                    mma8(acc[nt][0], acc[nt][1], acc[nt][2], acc[nt][3],
                         a0, a1, a2, a3, b.x, b.y);
                }
            }
            __syncthreads();                   /* prev chunk's GEMM2 H reads done */
            /* store H chunk as tf32 */
            #pragma unroll
            for (int nt = 0; nt < 8; ++nt) {
                const int col = nt*8 + 2*tig;
                uint2 lo; lo.x = to_tf32(acc[nt][0]); lo.y = to_tf32(acc[nt][1]);
                uint2 hi; hi.x = to_tf32(acc[nt][2]); hi.y = to_tf32(acc[nt][3]);
                *(uint2*)&Hsm[(rw+g)*HS + col]   = lo;
                *(uint2*)&Hsm[(rw+g+8)*HS + col] = hi;
            }
            __syncthreads();                   /* H visible */

            /* GEMM2: dacc += Hchunk * W1^T chunk */
            #pragma unroll
            for (int kt = 0; kt < 8; ++kt) {
                const int col = kt*8 + tig;
                uint32_t a0 = Hsm[(rw+g)*HS + col];
                uint32_t a1 = Hsm[(rw+g+8)*HS + col];
                uint32_t a2 = Hsm[(rw+g)*HS + col + 4];
                uint32_t a3 = Hsm[(rw+g+8)*HS + col + 4];
                const uint2* bf = w1f + ((nc*8 + kt)*4)*32 + lane;
                uint2 b;
                b = bf[0];   mma8(d0[0],d0[1],d0[2],d0[3], a0,a1,a2,a3, b.x,b.y);
                b = bf[32];  mma8(d1[0],d1[1],d1[2],d1[3], a0,a1,a2,a3, b.x,b.y);
                b = bf[64];  mma8(d2[0],d2[1],d2[2],d2[3], a0,a1,a2,a3, b.x,b.y);
                b = bf[96];  mma8(d3[0],d3[1],d3[2],d3[3], a0,a1,a2,a3, b.x,b.y);
            }
        }
        __syncthreads();                       /* all Y reads done; D may alias Y */

        /* ---- D -> smem ---- */
        {
            const int c0 = 2*tig;
            *(float2*)&Dsm[(rw+g)*DS + c0]        = make_float2(d0[0], d0[1]);
            *(float2*)&Dsm[(rw+g+8)*DS + c0]      = make_float2(d0[2], d0[3]);
            *(float2*)&Dsm[(rw+g)*DS + 8 + c0]    = make_float2(d1[0], d1[1]);
            *(float2*)&Dsm[(rw+g+8)*DS + 8 + c0]  = make_float2(d1[2], d1[3]);
            *(float2*)&Dsm[(rw+g)*DS + 16 + c0]   = make_float2(d2[0], d2[1]);
            *(float2*)&Dsm[(rw+g+8)*DS + 16 + c0] = make_float2(d2[2], d2[3]);
            *(float2*)&Dsm[(rw+g)*DS + 24 + c0]   = make_float2(d3[0], d3[1]);
            *(float2*)&Dsm[(rw+g+8)*DS + 24 + c0] = make_float2(d3[2], d3[3]);
        }
        __syncthreads();

        /* ---- epilogue: mask, sigmoid, store ---- */
        uint2 rb = threefry(fk.x, fk.y, 0u, (uint32_t)pg);
        uint32_t bits = rb.x ^ rb.y;
        float u = __uint_as_float((bits >> 9) | 0x3f800000u) - 1.0f;
        float m = (u > 0.5f) ? 1.0f : 0.0f;

        float outv[16];
        #pragma unroll
        for (int j = 0; j < 16; ++j) {
            int c = chb + j;
            float d = Dsm[p*DS + c] + c2[c];
            float t = xv[j] + d * m;
            float sg = __fdividef(1.0f, 1.0f + __expf(-t));
            outv[j] = (c < 3) ? xv[j] : sg;
        }
        if (OUTMODE == 0) {
            #pragma unroll
            for (int j = 0; j < 16; ++j)
                xout[(size_t)(chb + j) * NPIX + pg] = outv[j];
        } else {
            float* dst = xout + (size_t)pg * CN + chb;
            #pragma unroll
            for (int q = 0; q < 4; ++q)
                *(float4*)(dst + 4*q) = make_float4(outv[4*q], outv[4*q+1],
                                                    outv[4*q+2], outv[4*q+3]);
        }
        __syncthreads();                       /* epilogue D reads done before next Y store */
    }
}

/* ---------------- launch ---------------- */
extern "C" void kernel_launch(void* const* d_in, const int* in_sizes, int n_in,
                              void* d_out, int out_size)
{
    const float* x    = (const float*)d_in[0];
    const float* fc0w = (const float*)d_in[1];
    const float* fc0b = (const float*)d_in[2];
    const float* fc1w = (const float*)d_in[3];
    const int*   st   = (const int*)d_in[4];
    float* out = (float*)d_out;

    float *p0 = nullptr, *p1 = nullptr;
    cudaGetSymbolAddress((void**)&p0, g_p0);
    cudaGetSymbolAddress((void**)&p1, g_p1);

    int nsm = 148;
    cudaDeviceGetAttribute(&nsm, cudaDevAttrMultiProcessorCount, 0);

    cudaFuncSetAttribute((const void*)nca_mma<0>,
                         cudaFuncAttributeMaxDynamicSharedMemorySize, SMEM_BYTES);
    cudaFuncSetAttribute((const void*)nca_mma<1>,
                         cudaFuncAttributeMaxDynamicSharedMemorySize, SMEM_BYTES);

    aos_to_planar<<<NPIX / 32, 256>>>(x, p0);
    nca_mma<0><<<nsm, THREADS, SMEM_BYTES>>>(p0, p1,  fc0w, fc0b, fc1w, st, 0);
    nca_mma<1><<<nsm, THREADS, SMEM_BYTES>>>(p1, out, fc0w, fc0b, fc1w, st, 1);
}

// round 6
// speedup vs baseline: 2.3617x; 1.3305x over previous
#include <cuda_runtime.h>
#include <cstdint>

#define CN   32
#define HID  256
#define K3   96
#define WW   256
#define NPIX (8*256*256)         /* 524288 */
#define TILE 128
#define NTILES (NPIX/TILE)       /* 4096 */
#define THREADS 256

/* smem byte offsets */
#define W0F_B 0                  /* 6kt*32nt*32lane*8B  = 49152 */
#define W1F_B 49152              /* 16kt*4nt*32lane*8B  = 16384 */
#define Y_B   65536              /* 128 rows * 256 B (bf16, swizzled) = 32768 */
#define H_B   98304              /* 128 rows * 512 B (bf16, swizzled) = 65536 */
#define X_B   163840             /* 128*36 f32 = 18432 */
#define D_B   182272             /* 128*36 f32 = 18432 */
#define C2_B  200704             /* 32 f32 */
#define SMEM_BYTES 200832

/* planar (SoA) ping-pong scratch: [c][pix] */
__device__ float g_p0[(size_t)CN * NPIX];
__device__ float g_p1[(size_t)CN * NPIX];

/* ================= helpers ================= */
static __device__ __forceinline__ uint32_t smem_u32(const void* p) {
    uint32_t a;
    asm("{ .reg .u64 t; cvta.to.shared.u64 t, %1; cvt.u32.u64 %0, t; }" : "=r"(a) : "l"(p));
    return a;
}
/* pack two f32 -> bf16x2 (lo in low half, hi in high half) */
static __device__ __forceinline__ uint32_t pkbf(float hi, float lo) {
    uint32_t r;
    asm("cvt.rn.bf16x2.f32 %0, %1, %2;" : "=r"(r) : "f"(hi), "f"(lo));
    return r;
}
static __device__ __forceinline__ void ldsm4(uint32_t& r0, uint32_t& r1,
                                             uint32_t& r2, uint32_t& r3, uint32_t addr) {
    asm volatile("ldmatrix.sync.aligned.m8n8.x4.shared.b16 {%0,%1,%2,%3}, [%4];"
                 : "=r"(r0), "=r"(r1), "=r"(r2), "=r"(r3) : "r"(addr));
}
static __device__ __forceinline__ void mma16(float& d0, float& d1, float& d2, float& d3,
                                             uint32_t a0, uint32_t a1, uint32_t a2, uint32_t a3,
                                             uint32_t b0, uint32_t b1) {
    asm volatile("mma.sync.aligned.m16n8k16.row.col.f32.bf16.bf16.f32 "
                 "{%0,%1,%2,%3}, {%4,%5,%6,%7}, {%8,%9}, {%0,%1,%2,%3};"
                 : "+f"(d0), "+f"(d1), "+f"(d2), "+f"(d3)
                 : "r"(a0), "r"(a1), "r"(a2), "r"(a3), "r"(b0), "r"(b1));
}

/* ---------------- JAX threefry2x32 (validated R2) ---------------- */
static __device__ __forceinline__ uint2 threefry(uint32_t k0, uint32_t k1,
                                                 uint32_t x0, uint32_t x1) {
    uint32_t ks2 = k0 ^ k1 ^ 0x1BD11BDAu;
    x0 += k0; x1 += k1;
#define TF_R(r) { x0 += x1; x1 = __funnelshift_l(x1, x1, (r)); x1 ^= x0; }
    TF_R(13) TF_R(15) TF_R(26) TF_R(6)   x0 += k1;  x1 += ks2 + 1u;
    TF_R(17) TF_R(29) TF_R(16) TF_R(24)  x0 += ks2; x1 += k0  + 2u;
    TF_R(13) TF_R(15) TF_R(26) TF_R(6)   x0 += k0;  x1 += k1  + 3u;
    TF_R(17) TF_R(29) TF_R(16) TF_R(24)  x0 += k1;  x1 += ks2 + 4u;
    TF_R(13) TF_R(15) TF_R(26) TF_R(6)   x0 += ks2; x1 += k0  + 5u;
#undef TF_R
    return make_uint2(x0, x1);
}

/* ---------------- AoS [pix][32] -> planar [c][pix] ---------------- */
__global__ void __launch_bounds__(256, 4)
aos_to_planar(const float* __restrict__ src, float* __restrict__ dst)
{
    __shared__ float tile[CN][33];
    const int tid = threadIdx.x;
    const int base = blockIdx.x * 32;
    {
        const int p  = tid >> 3;
        const int cg = tid & 7;
        float4 v = *(const float4*)(src + ((size_t)(base + p)) * CN + cg * 4);
        tile[cg*4 + 0][p] = v.x;  tile[cg*4 + 1][p] = v.y;
        tile[cg*4 + 2][p] = v.z;  tile[cg*4 + 3][p] = v.w;
    }
    __syncthreads();
    {
        const int p = tid & 31;
        const int c0 = tid >> 5;
        #pragma unroll
        for (int i = 0; i < 4; ++i) {
            const int c = c0 + i * 8;
            dst[(size_t)c * NPIX + base + p] = tile[c][p];
        }
    }
}

/* ================= fused NCA step, bf16 m16n8k16 tensor cores ================= */
template <int OUTMODE>   /* 0 = planar out, 1 = AoS out (final) */
__global__ void __launch_bounds__(THREADS, 1)
nca_mma(const float* __restrict__ xin, float* __restrict__ xout,
        const float* __restrict__ fc0w, const float* __restrict__ fc0b,
        const float* __restrict__ fc1w, const int* __restrict__ stepsPtr,
        int stepIdx)
{
    extern __shared__ char smb[];
    const uint32_t su = smem_u32(smb);
    const int tid  = threadIdx.x;
    const int lane = tid & 31;
    const int warp = tid >> 5;
    const int S = *stepsPtr;
    const int p   = tid & 127;            /* pixel within tile (stencil/epilogue role) */
    const int chb = (tid >> 7) * 16;      /* channel half base */

    if (stepIdx >= S) {                   /* identity pass-through */
        for (int tile = blockIdx.x; tile < NTILES; tile += gridDim.x) {
            const int pg = tile * TILE + p;
            #pragma unroll
            for (int j = 0; j < 16; ++j) {
                int c = chb + j;
                float v = xin[(size_t)c * NPIX + pg];
                if (OUTMODE == 0) xout[(size_t)c * NPIX + pg] = v;
                else              xout[(size_t)pg * CN + c] = v;
            }
        }
        return;
    }

    /* -------- one-time: weight fragments (bf16) + bias fold -------- */
    uint2* w0f = (uint2*)(smb + W0F_B);   /* [(kt*32+nt)*32+lane] */
    for (int e = tid; e < 6*32*32; e += THREADS) {
        int kt = e >> 10, rem = e & 1023, nt = rem >> 5, t = rem & 31;
        int g = t >> 2, tg = t & 3;
        int n = nt*8 + g, k = kt*16 + 2*tg;
        uint2 v;
        v.x = pkbf(fc0w[n*K3 + k + 1], fc0w[n*K3 + k]);
        v.y = pkbf(fc0w[n*K3 + k + 9], fc0w[n*K3 + k + 8]);
        w0f[e] = v;
    }
    uint2* w1f = (uint2*)(smb + W1F_B);   /* [(kt*4+nt)*32+lane] */
    for (int e = tid; e < 16*4*32; e += THREADS) {
        int kt = e >> 7, rem = e & 127, nt = rem >> 5, t = rem & 31;
        int g = t >> 2, tg = t & 3;
        int n = nt*8 + g, k = kt*16 + 2*tg;
        uint2 v;
        v.x = pkbf(fc1w[n*HID + k + 1], fc1w[n*HID + k]);
        v.y = pkbf(fc1w[n*HID + k + 9], fc1w[n*HID + k + 8]);
        w1f[e] = v;
    }
    float* c2 = (float*)(smb + C2_B);
    if (tid < CN) {                        /* c2 = W1 * b (bias folded linearly) */
        float s = 0.f;
        const float* wr = fc1w + tid * HID;
        #pragma unroll 8
        for (int h2 = 0; h2 < HID; ++h2) s += wr[h2] * fc0b[h2];
        c2[tid] = s;
    }
    __syncthreads();

    float* Xsm = (float*)(smb + X_B);
    float* Dsm = (float*)(smb + D_B);

    const uint2 fk = threefry(0u, 42u, 0u, (uint32_t)stepIdx);
    const int g = lane >> 2, tig = lane & 3;
    const int mg = warp >> 2;              /* M-group: rows mg*64       */
    const int ng = warp & 3;               /* N-group: nt = ng*8 + ntl  */
    const int rw2 = warp * 16;             /* GEMM2 row base            */
    const uint32_t swz = (uint32_t)((lane & 7) << 4);

    for (int tile = blockIdx.x; tile < NTILES; tile += gridDim.x) {
        const int pg = tile * TILE + p;
        const int hrow = (pg >> 8) & 255;
        const int wc = pg & 255;
        const bool hu = (hrow > 0), hd = (hrow < 255);
        const bool wl = (wc > 0),  wr = (wc < 255);

        /* ---- stencil via warp shuffles; Y -> bf16 swizzled smem, X -> f32 smem ---- */
        {
            float xf[16], dxf[16], dyf[16];
            #pragma unroll
            for (int j = 0; j < 16; ++j) {
                const float* xc = xin + (size_t)(chb + j) * NPIX + pg;
                float uc = hu ? xc[-WW] : 0.f;
                float cc = xc[0];
                float bc = hd ? xc[ WW] : 0.f;
                float ul = __shfl_up_sync(0xffffffffu, uc, 1);
                float cl = __shfl_up_sync(0xffffffffu, cc, 1);
                float bl = __shfl_up_sync(0xffffffffu, bc, 1);
                if (lane == 0) {
                    ul = (hu && wl) ? xc[-WW-1] : 0.f;
                    cl =  wl        ? xc[-1]    : 0.f;
                    bl = (hd && wl) ? xc[ WW-1] : 0.f;
                }
                float ur = __shfl_down_sync(0xffffffffu, uc, 1);
                float cr = __shfl_down_sync(0xffffffffu, cc, 1);
                float br = __shfl_down_sync(0xffffffffu, bc, 1);
                if (lane == 31) {
                    ur = (hu && wr) ? xc[-WW+1] : 0.f;
                    cr =  wr        ? xc[ 1]    : 0.f;
                    br = (hd && wr) ? xc[ WW+1] : 0.f;
                }
                xf[j] = cc;
                dxf[j] = 0.125f * ((bl - ul) + 2.f * (bc - uc) + (br - ur));
                dyf[j] = 0.125f * ((ur - ul) + 2.f * (cr - cl) + (br - bl));
            }
            const uint32_t psw = (uint32_t)((p & 7) << 4);
            char* yrow = smb + Y_B + p * 256;
            #pragma unroll
            for (int q = 0; q < 2; ++q) {
                uint4 vx, vdx, vdy;
                vx.x  = pkbf(xf [8*q+1], xf [8*q+0]); vx.y  = pkbf(xf [8*q+3], xf [8*q+2]);
                vx.z  = pkbf(xf [8*q+5], xf [8*q+4]); vx.w  = pkbf(xf [8*q+7], xf [8*q+6]);
                vdx.x = pkbf(dxf[8*q+1], dxf[8*q+0]); vdx.y = pkbf(dxf[8*q+3], dxf[8*q+2]);
                vdx.z = pkbf(dxf[8*q+5], dxf[8*q+4]); vdx.w = pkbf(dxf[8*q+7], dxf[8*q+6]);
                vdy.x = pkbf(dyf[8*q+1], dyf[8*q+0]); vdy.y = pkbf(dyf[8*q+3], dyf[8*q+2]);
                vdy.z = pkbf(dyf[8*q+5], dyf[8*q+4]); vdy.w = pkbf(dyf[8*q+7], dyf[8*q+6]);
                uint32_t cb = (uint32_t)(chb*2 + q*16);
                *(uint4*)(yrow + ((  0 + cb) ^ psw)) = vx;
                *(uint4*)(yrow + (( 64 + cb) ^ psw)) = vdx;
                *(uint4*)(yrow + ((128 + cb) ^ psw)) = vdy;
            }
            #pragma unroll
            for (int q = 0; q < 4; ++q)
                *(float4*)&Xsm[p*36 + chb + 4*q] =
                    make_float4(xf[4*q], xf[4*q+1], xf[4*q+2], xf[4*q+3]);
        }
        __syncthreads();                       /* (1) Y visible */

        /* ---- GEMM1: H[128x256] = Y[128x96] x W0^T ; warp = (mg, ng) ---- */
        {
            float acc[4][8][4];
            #pragma unroll
            for (int rb = 0; rb < 4; ++rb)
                #pragma unroll
                for (int nl = 0; nl < 8; ++nl)
                    #pragma unroll
                    for (int q = 0; q < 4; ++q) acc[rb][nl][q] = 0.f;

            const uint32_t arow = (uint32_t)(mg*64 + (lane & 15));
            const uint32_t abase = su + Y_B + arow * 256;
            const uint32_t asw = (uint32_t)(((lane >> 4) * 16) ^ ((arow & 7) << 4));

            #pragma unroll
            for (int kt = 0; kt < 6; ++kt) {
                uint32_t a[4][4];
                #pragma unroll
                for (int rb = 0; rb < 4; ++rb)
                    ldsm4(a[rb][0], a[rb][1], a[rb][2], a[rb][3],
                          abase + rb*16*256 + ((uint32_t)(kt*32) ^ asw));
                const uint2* bf = w0f + (kt*32 + ng*8)*32 + lane;
                #pragma unroll
                for (int nl = 0; nl < 8; ++nl) {
                    uint2 b = bf[nl*32];
                    #pragma unroll
                    for (int rb = 0; rb < 4; ++rb)
                        mma16(acc[rb][nl][0], acc[rb][nl][1], acc[rb][nl][2], acc[rb][nl][3],
                              a[rb][0], a[rb][1], a[rb][2], a[rb][3], b.x, b.y);
                }
            }
            /* store H as bf16 (swizzled) */
            char* hb = smb + H_B;
            #pragma unroll
            for (int rb = 0; rb < 4; ++rb) {
                int r0 = mg*64 + rb*16 + g;
                #pragma unroll
                for (int nl = 0; nl < 8; ++nl) {
                    uint32_t cb = (uint32_t)(((ng*8 + nl)*16 + 4*tig) ^ (g << 4));
                    *(uint32_t*)(hb + r0*512 + cb)       = pkbf(acc[rb][nl][1], acc[rb][nl][0]);
                    *(uint32_t*)(hb + (r0+8)*512 + cb)   = pkbf(acc[rb][nl][3], acc[rb][nl][2]);
                }
            }
        }
        __syncthreads();                       /* (2) H visible */

        /* ---- GEMM2: D[128x32] = H x W1^T ; warp owns rows rw2..rw2+15 ---- */
        {
            float dacc[4][4];
            #pragma unroll
            for (int nt = 0; nt < 4; ++nt)
                #pragma unroll
                for (int q = 0; q < 4; ++q) dacc[nt][q] = 0.f;

            const uint32_t arow = (uint32_t)(rw2 + (lane & 15));
            const uint32_t abase = su + H_B + arow * 512;
            const uint32_t asw = (uint32_t)(((lane >> 4) * 16) ^ ((arow & 7) << 4));

            #pragma unroll
            for (int kt = 0; kt < 16; ++kt) {
                uint32_t a0, a1, a2, a3;
                ldsm4(a0, a1, a2, a3, abase + ((uint32_t)(kt*32) ^ asw));
                const uint2* bf = w1f + (kt*4)*32 + lane;
                #pragma unroll
                for (int nt = 0; nt < 4; ++nt) {
                    uint2 b = bf[nt*32];
                    mma16(dacc[nt][0], dacc[nt][1], dacc[nt][2], dacc[nt][3],
                          a0, a1, a2, a3, b.x, b.y);
                }
            }
            #pragma unroll
            for (int nt = 0; nt < 4; ++nt) {
                *(float2*)&Dsm[(rw2+g)*36   + nt*8 + 2*tig] = make_float2(dacc[nt][0], dacc[nt][1]);
                *(float2*)&Dsm[(rw2+g+8)*36 + nt*8 + 2*tig] = make_float2(dacc[nt][2], dacc[nt][3]);
            }
        }
        __syncthreads();                       /* (3) D visible */

        /* ---- epilogue: mask, sigmoid, store ---- */
        uint2 rb2 = threefry(fk.x, fk.y, 0u, (uint32_t)pg);
        uint32_t bits = rb2.x ^ rb2.y;
        float u = __uint_as_float((bits >> 9) | 0x3f800000u) - 1.0f;
        float m = (u > 0.5f) ? 1.0f : 0.0f;

        float outv[16];
        #pragma unroll
        for (int q = 0; q < 4; ++q) {
            float4 dv = *(const float4*)&Dsm[p*36 + chb + 4*q];
            float4 xv = *(const float4*)&Xsm[p*36 + chb + 4*q];
            float dd[4] = {dv.x, dv.y, dv.z, dv.w};
            float xx[4] = {xv.x, xv.y, xv.z, xv.w};
            #pragma unroll
            for (int e = 0; e < 4; ++e) {
                int c = chb + 4*q + e;
                float d = dd[e] + c2[c];
                float t = xx[e] + d * m;
                float sg = __fdividef(1.0f, 1.0f + __expf(-t));
                outv[4*q + e] = (c < 3) ? xx[e] : sg;
            }
        }
        if (OUTMODE == 0) {
            #pragma unroll
            for (int j = 0; j < 16; ++j)
                xout[(size_t)(chb + j) * NPIX + pg] = outv[j];
        } else {
            float* dst = xout + (size_t)pg * CN + chb;
            #pragma unroll
            for (int q = 0; q < 4; ++q)
                *(float4*)(dst + 4*q) = make_float4(outv[4*q], outv[4*q+1],
                                                    outv[4*q+2], outv[4*q+3]);
        }
        /* no sync needed here: next tile's smem writes are fenced by sync (1)/(2) */
    }
}

/* ---------------- launch ---------------- */
extern "C" void kernel_launch(void* const* d_in, const int* in_sizes, int n_in,
                              void* d_out, int out_size)
{
    const float* x    = (const float*)d_in[0];
    const float* fc0w = (const float*)d_in[1];
    const float* fc0b = (const float*)d_in[2];
    const float* fc1w = (const float*)d_in[3];
    const int*   st   = (const int*)d_in[4];
    float* out = (float*)d_out;

    float *p0 = nullptr, *p1 = nullptr;
    cudaGetSymbolAddress((void**)&p0, g_p0);
    cudaGetSymbolAddress((void**)&p1, g_p1);

    int nsm = 148;
    cudaDeviceGetAttribute(&nsm, cudaDevAttrMultiProcessorCount, 0);

    cudaFuncSetAttribute((const void*)nca_mma<0>,
                         cudaFuncAttributeMaxDynamicSharedMemorySize, SMEM_BYTES);
    cudaFuncSetAttribute((const void*)nca_mma<1>,
                         cudaFuncAttributeMaxDynamicSharedMemorySize, SMEM_BYTES);

    aos_to_planar<<<NPIX / 32, 256>>>(x, p0);
    nca_mma<0><<<nsm, THREADS, SMEM_BYTES>>>(p0, p1,  fc0w, fc0b, fc1w, st, 0);
    nca_mma<1><<<nsm, THREADS, SMEM_BYTES>>>(p1, out, fc0w, fc0b, fc1w, st, 1);
}

// round 7
// speedup vs baseline: 3.2331x; 1.3690x over previous
#include <cuda_runtime.h>
#include <cstdint>

#define CN   32
#define HID  256
#define K3   96
#define WW   256
#define NPIX (8*256*256)         /* 524288 */
#define TILE 128
#define NTILES (NPIX/TILE)       /* 4096 */
#define THREADS 256

/* smem byte offsets */
#define W0F_B 0                  /* 6kt*32nt*32lane*8B  = 49152 */
#define W1F_B 49152              /* 16kt*4nt*32lane*8B  = 16384 */
#define Y_B   65536              /* 128 rows * 256 B (bf16, swizzled) = 32768 */
#define D_B   Y_B                /* D aliases Y: 128*36*4 = 18432 */
#define H_B   98304              /* 128 rows * 512 B (bf16, swizzled) = 65536 */
#define XS_B  163840             /* 3*130*36 f32 = 56160 */
#define C2_B  220000             /* 32 f32 */
#define SMEM_BYTES 220160

#define XSP 36                   /* XS channel-pad stride (36%32==4 -> conflict-free) */

/* planar (SoA) ping-pong scratch: [c][pix] */
__device__ float g_p0[(size_t)CN * NPIX];
__device__ float g_p1[(size_t)CN * NPIX];

/* ================= helpers ================= */
static __device__ __forceinline__ uint32_t smem_u32(const void* p) {
    uint32_t a;
    asm("{ .reg .u64 t; cvta.to.shared.u64 t, %1; cvt.u32.u64 %0, t; }" : "=r"(a) : "l"(p));
    return a;
}
static __device__ __forceinline__ uint32_t pkbf(float hi, float lo) {
    uint32_t r;
    asm("cvt.rn.bf16x2.f32 %0, %1, %2;" : "=r"(r) : "f"(hi), "f"(lo));
    return r;
}
static __device__ __forceinline__ void ldsm4(uint32_t& r0, uint32_t& r1,
                                             uint32_t& r2, uint32_t& r3, uint32_t addr) {
    asm volatile("ldmatrix.sync.aligned.m8n8.x4.shared.b16 {%0,%1,%2,%3}, [%4];"
                 : "=r"(r0), "=r"(r1), "=r"(r2), "=r"(r3) : "r"(addr));
}
static __device__ __forceinline__ void mma16(float& d0, float& d1, float& d2, float& d3,
                                             uint32_t a0, uint32_t a1, uint32_t a2, uint32_t a3,
                                             uint32_t b0, uint32_t b1) {
    asm volatile("mma.sync.aligned.m16n8k16.row.col.f32.bf16.bf16.f32 "
                 "{%0,%1,%2,%3}, {%4,%5,%6,%7}, {%8,%9}, {%0,%1,%2,%3};"
                 : "+f"(d0), "+f"(d1), "+f"(d2), "+f"(d3)
                 : "r"(a0), "r"(a1), "r"(a2), "r"(a3), "r"(b0), "r"(b1));
}
static __device__ __forceinline__ void cp4(uint32_t saddr, const float* g, bool inb) {
    int sz = inb ? 4 : 0;
    asm volatile("cp.async.ca.shared.global [%0], [%1], 4, %2;"
                 :: "r"(saddr), "l"(g), "r"(sz) : "memory");
}
#define CP_COMMIT() asm volatile("cp.async.commit_group;" ::: "memory")
#define CP_WAIT0()  asm volatile("cp.async.wait_group 0;" ::: "memory")

/* ---------------- JAX threefry2x32 (validated R2) ---------------- */
static __device__ __forceinline__ uint2 threefry(uint32_t k0, uint32_t k1,
                                                 uint32_t x0, uint32_t x1) {
    uint32_t ks2 = k0 ^ k1 ^ 0x1BD11BDAu;
    x0 += k0; x1 += k1;
#define TF_R(r) { x0 += x1; x1 = __funnelshift_l(x1, x1, (r)); x1 ^= x0; }
    TF_R(13) TF_R(15) TF_R(26) TF_R(6)   x0 += k1;  x1 += ks2 + 1u;
    TF_R(17) TF_R(29) TF_R(16) TF_R(24)  x0 += ks2; x1 += k0  + 2u;
    TF_R(13) TF_R(15) TF_R(26) TF_R(6)   x0 += k0;  x1 += k1  + 3u;
    TF_R(17) TF_R(29) TF_R(16) TF_R(24)  x0 += k1;  x1 += ks2 + 4u;
    TF_R(13) TF_R(15) TF_R(26) TF_R(6)   x0 += ks2; x1 += k0  + 5u;
#undef TF_R
    return make_uint2(x0, x1);
}

/* pad kernel: shifts ncu launch index so -s 5 lands on a step kernel */
__global__ void pad_kernel() {}

/* ---------------- AoS [pix][32] -> planar [c][pix] ---------------- */
__global__ void __launch_bounds__(256, 4)
aos_to_planar(const float* __restrict__ src, float* __restrict__ dst)
{
    __shared__ float tile[CN][33];
    const int tid = threadIdx.x;
    const int base = blockIdx.x * 32;
    {
        const int p  = tid >> 3;
        const int cg = tid & 7;
        float4 v = *(const float4*)(src + ((size_t)(base + p)) * CN + cg * 4);
        tile[cg*4 + 0][p] = v.x;  tile[cg*4 + 1][p] = v.y;
        tile[cg*4 + 2][p] = v.z;  tile[cg*4 + 3][p] = v.w;
    }
    __syncthreads();
    {
        const int p = tid & 31;
        const int c0 = tid >> 5;
        #pragma unroll
        for (int i = 0; i < 4; ++i) {
            const int c = c0 + i * 8;
            dst[(size_t)c * NPIX + base + p] = tile[c][p];
        }
    }
}

/* stage tile T's 3x130x32 stencil window into XS via cp.async (zfill pads) */
static __device__ __forceinline__ void stage_tile(const float* __restrict__ xin,
                                                  uint32_t su, int T, int tid)
{
    const int pgb = T * TILE;
    const int rowg = pgb >> 8;            /* global row incl batch */
    const int h = rowg & 255;
    const int wb = pgb & 255;             /* 0 or 128 */
    #pragma unroll 1
    for (int e = tid; e < 3*130*32; e += THREADS) {
        int r = e / 4160;
        int rem = e - r * 4160;
        int px = rem >> 5;
        int c = rem & 31;
        int ri = h + r - 1;
        int wcoord = wb + px - 1;
        bool inb = (ri >= 0) && (ri < 256) && (wcoord >= 0) && (wcoord < 256);
        const float* g = inb ? (xin + (size_t)c * NPIX + (((size_t)(rowg + r - 1)) << 8) + wcoord)
                             : xin;
        uint32_t sa = su + XS_B + (uint32_t)(((r * 130 + px) * XSP + c) << 2);
        cp4(sa, g, inb);
    }
    CP_COMMIT();
}

/* ================= fused NCA step, pipelined bf16 tensor cores ================= */
template <int OUTMODE>   /* 0 = planar out, 1 = AoS out (final) */
__global__ void __launch_bounds__(THREADS, 1)
nca_mma(const float* __restrict__ xin, float* __restrict__ xout,
        const float* __restrict__ fc0w, const float* __restrict__ fc0b,
        const float* __restrict__ fc1w, const int* __restrict__ stepsPtr,
        int stepIdx)
{
    extern __shared__ char smb[];
    const uint32_t su = smem_u32(smb);
    const int tid  = threadIdx.x;
    const int lane = tid & 31;
    const int warp = tid >> 5;
    const int S = *stepsPtr;
    const int p   = tid & 127;            /* pixel within tile */
    const int chb = (tid >> 7) * 16;      /* channel half base */

    if (stepIdx >= S) {                   /* identity pass-through */
        for (int tile = blockIdx.x; tile < NTILES; tile += gridDim.x) {
            const int pg = tile * TILE + p;
            #pragma unroll
            for (int j = 0; j < 16; ++j) {
                int c = chb + j;
                float v = xin[(size_t)c * NPIX + pg];
                if (OUTMODE == 0) xout[(size_t)c * NPIX + pg] = v;
                else              xout[(size_t)pg * CN + c] = v;
            }
        }
        return;
    }

    /* -------- one-time: weight fragments (bf16) + bias fold -------- */
    uint2* w0f = (uint2*)(smb + W0F_B);
    for (int e = tid; e < 6*32*32; e += THREADS) {
        int kt = e >> 10, rem = e & 1023, nt = rem >> 5, t = rem & 31;
        int gg = t >> 2, tg = t & 3;
        int n = nt*8 + gg, k = kt*16 + 2*tg;
        uint2 v;
        v.x = pkbf(fc0w[n*K3 + k + 1], fc0w[n*K3 + k]);
        v.y = pkbf(fc0w[n*K3 + k + 9], fc0w[n*K3 + k + 8]);
        w0f[e] = v;
    }
    uint2* w1f = (uint2*)(smb + W1F_B);
    for (int e = tid; e < 16*4*32; e += THREADS) {
        int kt = e >> 7, rem = e & 127, nt = rem >> 5, t = rem & 31;
        int gg = t >> 2, tg = t & 3;
        int n = nt*8 + gg, k = kt*16 + 2*tg;
        uint2 v;
        v.x = pkbf(fc1w[n*HID + k + 1], fc1w[n*HID + k]);
        v.y = pkbf(fc1w[n*HID + k + 9], fc1w[n*HID + k + 8]);
        w1f[e] = v;
    }
    float* c2 = (float*)(smb + C2_B);
    if (tid < CN) {                        /* c2 = W1 * b */
        float s = 0.f;
        const float* wr = fc1w + tid * HID;
        #pragma unroll 8
        for (int h2 = 0; h2 < HID; ++h2) s += wr[h2] * fc0b[h2];
        c2[tid] = s;
    }

    const float* XSf = (const float*)(smb + XS_B);
    float* Dsm = (float*)(smb + D_B);

    const uint2 fk = threefry(0u, 42u, 0u, (uint32_t)stepIdx);
    const int g = lane >> 2, tig = lane & 3;
    const int mg = warp >> 2;              /* M-group: rows mg*64      */
    const int ng = warp & 3;               /* N-group                  */
    const int rw2 = warp * 16;             /* GEMM2 row base           */

    /* prologue: stage first tile */
    int tile0 = blockIdx.x;
    if (tile0 < NTILES) stage_tile(xin, su, tile0, tid);
    CP_WAIT0();
    __syncthreads();

    for (int tile = tile0; tile < NTILES; tile += gridDim.x) {
        const int pg = tile * TILE + p;

        /* ---- stencil from staged smem (zero-padded) ; Y -> bf16 swizzled ---- */
        float xf[16];
        {
            float dxf[16], dyf[16];
            #pragma unroll
            for (int q = 0; q < 4; ++q) {
                const int c0 = chb + 4*q;
                float4 m00 = *(const float4*)&XSf[(0*130 + p    )*XSP + c0];
                float4 m01 = *(const float4*)&XSf[(0*130 + p + 1)*XSP + c0];
                float4 m02 = *(const float4*)&XSf[(0*130 + p + 2)*XSP + c0];
                float4 m10 = *(const float4*)&XSf[(1*130 + p    )*XSP + c0];
                float4 m11 = *(const float4*)&XSf[(1*130 + p + 1)*XSP + c0];
                float4 m12 = *(const float4*)&XSf[(1*130 + p + 2)*XSP + c0];
                float4 m20 = *(const float4*)&XSf[(2*130 + p    )*XSP + c0];
                float4 m21 = *(const float4*)&XSf[(2*130 + p + 1)*XSP + c0];
                float4 m22 = *(const float4*)&XSf[(2*130 + p + 2)*XSP + c0];
                #pragma unroll
                for (int e = 0; e < 4; ++e) {
                    float ul = ((const float*)&m00)[e], uc = ((const float*)&m01)[e], ur = ((const float*)&m02)[e];
                    float cl = ((const float*)&m10)[e], cc = ((const float*)&m11)[e], cr = ((const float*)&m12)[e];
                    float bl = ((const float*)&m20)[e], bc = ((const float*)&m21)[e], br = ((const float*)&m22)[e];
                    xf[4*q+e]  = cc;
                    dxf[4*q+e] = 0.125f * ((bl - ul) + 2.f * (bc - uc) + (br - ur));
                    dyf[4*q+e] = 0.125f * ((ur - ul) + 2.f * (cr - cl) + (br - bl));
                }
            }
            const uint32_t psw = (uint32_t)((p & 7) << 4);
            char* yrow = smb + Y_B + p * 256;
            #pragma unroll
            for (int q = 0; q < 2; ++q) {
                uint4 vx, vdx, vdy;
                vx.x  = pkbf(xf [8*q+1], xf [8*q+0]); vx.y  = pkbf(xf [8*q+3], xf [8*q+2]);
                vx.z  = pkbf(xf [8*q+5], xf [8*q+4]); vx.w  = pkbf(xf [8*q+7], xf [8*q+6]);
                vdx.x = pkbf(dxf[8*q+1], dxf[8*q+0]); vdx.y = pkbf(dxf[8*q+3], dxf[8*q+2]);
                vdx.z = pkbf(dxf[8*q+5], dxf[8*q+4]); vdx.w = pkbf(dxf[8*q+7], dxf[8*q+6]);
                vdy.x = pkbf(dyf[8*q+1], dyf[8*q+0]); vdy.y = pkbf(dyf[8*q+3], dyf[8*q+2]);
                vdy.z = pkbf(dyf[8*q+5], dyf[8*q+4]); vdy.w = pkbf(dyf[8*q+7], dyf[8*q+6]);
                uint32_t cb = (uint32_t)(chb*2 + q*16);
                *(uint4*)(yrow + ((  0 + cb) ^ psw)) = vx;
                *(uint4*)(yrow + (( 64 + cb) ^ psw)) = vdx;
                *(uint4*)(yrow + ((128 + cb) ^ psw)) = vdy;
            }
        }
        __syncthreads();                       /* (1) Y visible; XS reads done */

        /* ---- stage NEXT tile (overlaps the GEMMs below) ---- */
        {
            int nt = tile + gridDim.x;
            if (nt < NTILES) stage_tile(xin, su, nt, tid);
            else CP_COMMIT();
        }

        /* ---- GEMM1: H[128x256] = Y[128x96] x W0^T ; warp = (mg, ng) ---- */
        {
            float acc[4][8][4];
            #pragma unroll
            for (int rb = 0; rb < 4; ++rb)
                #pragma unroll
                for (int nl = 0; nl < 8; ++nl)
                    #pragma unroll
                    for (int q = 0; q < 4; ++q) acc[rb][nl][q] = 0.f;

            const uint32_t arow = (uint32_t)(mg*64 + (lane & 15));
            const uint32_t abase = su + Y_B + arow * 256;
            const uint32_t asw = (uint32_t)(((lane >> 4) * 16) ^ ((arow & 7) << 4));

            #pragma unroll
            for (int kt = 0; kt < 6; ++kt) {
                uint32_t a[4][4];
                #pragma unroll
                for (int rb = 0; rb < 4; ++rb)
                    ldsm4(a[rb][0], a[rb][1], a[rb][2], a[rb][3],
                          abase + rb*16*256 + ((uint32_t)(kt*32) ^ asw));
                const uint2* bf = w0f + (kt*32 + ng*8)*32 + lane;
                #pragma unroll
                for (int nl = 0; nl < 8; ++nl) {
                    uint2 b = bf[nl*32];
                    #pragma unroll
                    for (int rb = 0; rb < 4; ++rb)
                        mma16(acc[rb][nl][0], acc[rb][nl][1], acc[rb][nl][2], acc[rb][nl][3],
                              a[rb][0], a[rb][1], a[rb][2], a[rb][3], b.x, b.y);
                }
            }
            char* hb = smb + H_B;
            #pragma unroll
            for (int rb = 0; rb < 4; ++rb) {
                int r0 = mg*64 + rb*16 + g;
                #pragma unroll
                for (int nl = 0; nl < 8; ++nl) {
                    uint32_t cb = (uint32_t)(((ng*8 + nl)*16 + 4*tig) ^ (g << 4));
                    *(uint32_t*)(hb + r0*512 + cb)     = pkbf(acc[rb][nl][1], acc[rb][nl][0]);
                    *(uint32_t*)(hb + (r0+8)*512 + cb) = pkbf(acc[rb][nl][3], acc[rb][nl][2]);
                }
            }
        }
        __syncthreads();                       /* (2) H visible */

        /* ---- GEMM2: D[128x32] = H x W1^T ; warp owns rows rw2..rw2+15 ---- */
        {
            float dacc[4][4];
            #pragma unroll
            for (int nt = 0; nt < 4; ++nt)
                #pragma unroll
                for (int q = 0; q < 4; ++q) dacc[nt][q] = 0.f;

            const uint32_t arow = (uint32_t)(rw2 + (lane & 15));
            const uint32_t abase = su + H_B + arow * 512;
            const uint32_t asw = (uint32_t)(((lane >> 4) * 16) ^ ((arow & 7) << 4));

            #pragma unroll
            for (int kt = 0; kt < 16; ++kt) {
                uint32_t a0, a1, a2, a3;
                ldsm4(a0, a1, a2, a3, abase + ((uint32_t)(kt*32) ^ asw));
                const uint2* bf = w1f + (kt*4)*32 + lane;
                #pragma unroll
                for (int nt = 0; nt < 4; ++nt) {
                    uint2 b = bf[nt*32];
                    mma16(dacc[nt][0], dacc[nt][1], dacc[nt][2], dacc[nt][3],
                          a0, a1, a2, a3, b.x, b.y);
                }
            }
            #pragma unroll
            for (int nt = 0; nt < 4; ++nt) {
                *(float2*)&Dsm[(rw2+g)*36   + nt*8 + 2*tig] = make_float2(dacc[nt][0], dacc[nt][1]);
                *(float2*)&Dsm[(rw2+g+8)*36 + nt*8 + 2*tig] = make_float2(dacc[nt][2], dacc[nt][3]);
            }
        }
        __syncthreads();                       /* (3) D visible */

        /* ---- epilogue: mask, sigmoid, store ---- */
        uint2 rb2 = threefry(fk.x, fk.y, 0u, (uint32_t)pg);
        uint32_t bits = rb2.x ^ rb2.y;
        float u = __uint_as_float((bits >> 9) | 0x3f800000u) - 1.0f;
        float m = (u > 0.5f) ? 1.0f : 0.0f;

        float outv[16];
        #pragma unroll
        for (int q = 0; q < 4; ++q) {
            float4 dv = *(const float4*)&Dsm[p*36 + chb + 4*q];
            float dd[4] = {dv.x, dv.y, dv.z, dv.w};
            #pragma unroll
            for (int e = 0; e < 4; ++e) {
                int c = chb + 4*q + e;
                float xx = xf[4*q + e];
                float d = dd[e] + c2[c];
                float t = xx + d * m;
                float sg = __fdividef(1.0f, 1.0f + __expf(-t));
                outv[4*q + e] = (c < 3) ? xx : sg;
            }
        }
        if (OUTMODE == 0) {
            #pragma unroll
            for (int j = 0; j < 16; ++j)
                xout[(size_t)(chb + j) * NPIX + pg] = outv[j];
        } else {
            float* dst = xout + (size_t)pg * CN + chb;
            #pragma unroll
            for (int q = 0; q < 4; ++q)
                *(float4*)(dst + 4*q) = make_float4(outv[4*q], outv[4*q+1],
                                                    outv[4*q+2], outv[4*q+3]);
        }

        CP_WAIT0();
        __syncthreads();                       /* (4) XS(t+1) ready; D reads done */
    }
}

/* ---------------- launch ---------------- */
extern "C" void kernel_launch(void* const* d_in, const int* in_sizes, int n_in,
                              void* d_out, int out_size)
{
    const float* x    = (const float*)d_in[0];
    const float* fc0w = (const float*)d_in[1];
    const float* fc0b = (const float*)d_in[2];
    const float* fc1w = (const float*)d_in[3];
    const int*   st   = (const int*)d_in[4];
    float* out = (float*)d_out;

    float *p0 = nullptr, *p1 = nullptr;
    cudaGetSymbolAddress((void**)&p0, g_p0);
    cudaGetSymbolAddress((void**)&p1, g_p1);

    int nsm = 148;
    cudaDeviceGetAttribute(&nsm, cudaDevAttrMultiProcessorCount, 0);

    cudaFuncSetAttribute((const void*)nca_mma<0>,
                         cudaFuncAttributeMaxDynamicSharedMemorySize, SMEM_BYTES);
    cudaFuncSetAttribute((const void*)nca_mma<1>,
                         cudaFuncAttributeMaxDynamicSharedMemorySize, SMEM_BYTES);

    pad_kernel<<<1, 32>>>();
    aos_to_planar<<<NPIX / 32, 256>>>(x, p0);
    nca_mma<0><<<nsm, THREADS, SMEM_BYTES>>>(p0, p1,  fc0w, fc0b, fc1w, st, 0);
    nca_mma<1><<<nsm, THREADS, SMEM_BYTES>>>(p1, out, fc0w, fc0b, fc1w, st, 1);
}

// round 8
// speedup vs baseline: 4.4785x; 1.3852x over previous
#include <cuda_runtime.h>
#include <cstdint>

#define CN   32
#define HID  256
#define K3   96
#define WW   256
#define NPIX (8*256*256)         /* 524288 */
#define TILE 128
#define NTILES (NPIX/TILE)       /* 4096 */
#define THREADS 256

/* smem byte offsets */
#define W0F_B 0                  /* 6kt*32nt*32lane*8B  = 49152 */
#define W1F_B 49152              /* 16kt*4nt*32lane*8B  = 16384 */
#define Y_B   65536              /* 128 rows * 256 B (bf16, swizzled) = 32768 */
#define D_B   Y_B                /* D aliases Y: 128*36*4 = 18432 */
#define H_B   98304              /* 128 rows * 512 B (bf16, swizzled) = 65536 */
#define XS_B  163840             /* [r][c][136] f32: 96*136*4 = 52224 */
#define C2_B  216064             /* 32 f32 */
#define SMEM_BYTES 216192

#define XSR 136                  /* XS px stride per (r,c) row */

/* planar (SoA) ping-pong scratch: [c][pix] */
__device__ float g_p0[(size_t)CN * NPIX];
__device__ float g_p1[(size_t)CN * NPIX];

/* ================= helpers ================= */
static __device__ __forceinline__ uint32_t smem_u32(const void* p) {
    uint32_t a;
    asm("{ .reg .u64 t; cvta.to.shared.u64 t, %1; cvt.u32.u64 %0, t; }" : "=r"(a) : "l"(p));
    return a;
}
static __device__ __forceinline__ uint32_t pkbf(float hi, float lo) {
    uint32_t r;
    asm("cvt.rn.bf16x2.f32 %0, %1, %2;" : "=r"(r) : "f"(hi), "f"(lo));
    return r;
}
static __device__ __forceinline__ void ldsm4(uint32_t& r0, uint32_t& r1,
                                             uint32_t& r2, uint32_t& r3, uint32_t addr) {
    asm volatile("ldmatrix.sync.aligned.m8n8.x4.shared.b16 {%0,%1,%2,%3}, [%4];"
                 : "=r"(r0), "=r"(r1), "=r"(r2), "=r"(r3) : "r"(addr));
}
static __device__ __forceinline__ void mma16(float& d0, float& d1, float& d2, float& d3,
                                             uint32_t a0, uint32_t a1, uint32_t a2, uint32_t a3,
                                             uint32_t b0, uint32_t b1) {
    asm volatile("mma.sync.aligned.m16n8k16.row.col.f32.bf16.bf16.f32 "
                 "{%0,%1,%2,%3}, {%4,%5,%6,%7}, {%8,%9}, {%0,%1,%2,%3};"
                 : "+f"(d0), "+f"(d1), "+f"(d2), "+f"(d3)
                 : "r"(a0), "r"(a1), "r"(a2), "r"(a3), "r"(b0), "r"(b1));
}
static __device__ __forceinline__ void cp4(uint32_t saddr, const float* g, bool inb) {
    int sz = inb ? 4 : 0;
    asm volatile("cp.async.ca.shared.global [%0], [%1], 4, %2;"
                 :: "r"(saddr), "l"(g), "r"(sz) : "memory");
}
static __device__ __forceinline__ void cp16(uint32_t saddr, const float* g, bool inb) {
    int sz = inb ? 16 : 0;
    asm volatile("cp.async.cg.shared.global [%0], [%1], 16, %2;"
                 :: "r"(saddr), "l"(g), "r"(sz) : "memory");
}
#define CP_COMMIT() asm volatile("cp.async.commit_group;" ::: "memory")
#define CP_WAIT0()  asm volatile("cp.async.wait_group 0;" ::: "memory")

/* ---------------- JAX threefry2x32 (validated R2) ---------------- */
static __device__ __forceinline__ uint2 threefry(uint32_t k0, uint32_t k1,
                                                 uint32_t x0, uint32_t x1) {
    uint32_t ks2 = k0 ^ k1 ^ 0x1BD11BDAu;
    x0 += k0; x1 += k1;
#define TF_R(r) { x0 += x1; x1 = __funnelshift_l(x1, x1, (r)); x1 ^= x0; }
    TF_R(13) TF_R(15) TF_R(26) TF_R(6)   x0 += k1;  x1 += ks2 + 1u;
    TF_R(17) TF_R(29) TF_R(16) TF_R(24)  x0 += ks2; x1 += k0  + 2u;
    TF_R(13) TF_R(15) TF_R(26) TF_R(6)   x0 += k0;  x1 += k1  + 3u;
    TF_R(17) TF_R(29) TF_R(16) TF_R(24)  x0 += k1;  x1 += ks2 + 4u;
    TF_R(13) TF_R(15) TF_R(26) TF_R(6)   x0 += ks2; x1 += k0  + 5u;
#undef TF_R
    return make_uint2(x0, x1);
}

/* pad kernel: shifts ncu launch index so -s 5 lands on a step kernel */
__global__ void pad_kernel() {}

/* ---------------- AoS [pix][32] -> planar [c][pix] ---------------- */
__global__ void __launch_bounds__(256, 4)
aos_to_planar(const float* __restrict__ src, float* __restrict__ dst)
{
    __shared__ float tile[CN][33];
    const int tid = threadIdx.x;
    const int base = blockIdx.x * 32;
    {
        const int p  = tid >> 3;
        const int cg = tid & 7;
        float4 v = *(const float4*)(src + ((size_t)(base + p)) * CN + cg * 4);
        tile[cg*4 + 0][p] = v.x;  tile[cg*4 + 1][p] = v.y;
        tile[cg*4 + 2][p] = v.z;  tile[cg*4 + 3][p] = v.w;
    }
    __syncthreads();
    {
        const int p = tid & 31;
        const int c0 = tid >> 5;
        #pragma unroll
        for (int i = 0; i < 4; ++i) {
            const int c = c0 + i * 8;
            dst[(size_t)c * NPIX + base + p] = tile[c][p];
        }
    }
}

/* stage tile T's stencil window as [r][c][px] (coalesced 16B cp.async) */
static __device__ __forceinline__ void stage_tile(const float* __restrict__ xin,
                                                  uint32_t su, int T, int tid)
{
    const int pgb = T * TILE;
    const int rowg = pgb >> 8;            /* global row incl batch */
    const int h = rowg & 255;
    const int wb = pgb & 255;             /* 0 or 128 */
    /* interior: 96 (r,c) pairs x 32 x 16B chunks, lane-contiguous over px */
    #pragma unroll
    for (int it = 0; it < 12; ++it) {
        int u = tid + it * THREADS;       /* 0..3071 */
        int pair = u >> 5;                /* r*32 + c */
        int k    = u & 31;
        int r = pair >> 5, c = pair & 31;
        int ri = h + r - 1;
        bool inb = (ri >= 0) && (ri < 256);
        const float* g = inb ? (xin + (size_t)c * NPIX + (((size_t)(rowg + r - 1)) << 8) + wb + 4*k)
                             : xin;
        uint32_t sa = su + XS_B + (uint32_t)((pair * XSR + 4 + 4*k) << 2);
        cp16(sa, g, inb);
    }
    /* edges: px=0 (idx 3) and px=129 (idx 132) */
    if (tid < 192) {
        int pair = tid >> 1, side = tid & 1;
        int r = pair >> 5, c = pair & 31;
        int ri = h + r - 1;
        int wcoord = side ? (wb + 128) : (wb - 1);
        bool inb = (ri >= 0) && (ri < 256) && (wcoord >= 0) && (wcoord < 256);
        const float* g = inb ? (xin + (size_t)c * NPIX + (((size_t)(rowg + r - 1)) << 8) + wcoord)
                             : xin;
        uint32_t sa = su + XS_B + (uint32_t)((pair * XSR + (side ? 132 : 3)) << 2);
        cp4(sa, g, inb);
    }
    CP_COMMIT();
}

/* ================= fused NCA step, pipelined bf16 tensor cores ================= */
template <int OUTMODE>   /* 0 = planar out, 1 = AoS out (final) */
__global__ void __launch_bounds__(THREADS, 1)
nca_mma(const float* __restrict__ xin, float* __restrict__ xout,
        const float* __restrict__ fc0w, const float* __restrict__ fc0b,
        const float* __restrict__ fc1w, const int* __restrict__ stepsPtr,
        int stepIdx)
{
    extern __shared__ char smb[];
    const uint32_t su = smem_u32(smb);
    const int tid  = threadIdx.x;
    const int lane = tid & 31;
    const int warp = tid >> 5;
    const int S = *stepsPtr;
    const int p   = tid & 127;            /* pixel within tile */
    const int chb = (tid >> 7) * 16;      /* channel half base */

    if (stepIdx >= S) {                   /* identity pass-through */
        for (int tile = blockIdx.x; tile < NTILES; tile += gridDim.x) {
            const int pg = tile * TILE + p;
            #pragma unroll
            for (int j = 0; j < 16; ++j) {
                int c = chb + j;
                float v = xin[(size_t)c * NPIX + pg];
                if (OUTMODE == 0) xout[(size_t)c * NPIX + pg] = v;
                else              xout[(size_t)pg * CN + c] = v;
            }
        }
        return;
    }

    /* -------- one-time: weight fragments (bf16) + bias fold -------- */
    uint2* w0f = (uint2*)(smb + W0F_B);
    for (int e = tid; e < 6*32*32; e += THREADS) {
        int kt = e >> 10, rem = e & 1023, nt = rem >> 5, t = rem & 31;
        int gg = t >> 2, tg = t & 3;
        int n = nt*8 + gg, k = kt*16 + 2*tg;
        uint2 v;
        v.x = pkbf(fc0w[n*K3 + k + 1], fc0w[n*K3 + k]);
        v.y = pkbf(fc0w[n*K3 + k + 9], fc0w[n*K3 + k + 8]);
        w0f[e] = v;
    }
    uint2* w1f = (uint2*)(smb + W1F_B);
    for (int e = tid; e < 16*4*32; e += THREADS) {
        int kt = e >> 7, rem = e & 127, nt = rem >> 5, t = rem & 31;
        int gg = t >> 2, tg = t & 3;
        int n = nt*8 + gg, k = kt*16 + 2*tg;
        uint2 v;
        v.x = pkbf(fc1w[n*HID + k + 1], fc1w[n*HID + k]);
        v.y = pkbf(fc1w[n*HID + k + 9], fc1w[n*HID + k + 8]);
        w1f[e] = v;
    }
    float* c2 = (float*)(smb + C2_B);
    if (tid < CN) {                        /* c2 = W1 * b */
        float s = 0.f;
        const float* wr = fc1w + tid * HID;
        #pragma unroll 8
        for (int h2 = 0; h2 < HID; ++h2) s += wr[h2] * fc0b[h2];
        c2[tid] = s;
    }

    const float* XSf = (const float*)(smb + XS_B);
    float* Dsm = (float*)(smb + D_B);

    const uint2 fk = threefry(0u, 42u, 0u, (uint32_t)stepIdx);
    const int g = lane >> 2, tig = lane & 3;
    const int mg = warp >> 2;              /* M-group: rows mg*64      */
    const int ng = warp & 3;               /* N-group                  */
    const int rw2 = warp * 16;             /* GEMM2 row base           */

    /* prologue: stage first tile */
    int tile0 = blockIdx.x;
    if (tile0 < NTILES) stage_tile(xin, su, tile0, tid);
    CP_WAIT0();
    __syncthreads();

    for (int tile = tile0; tile < NTILES; tile += gridDim.x) {
        const int pg = tile * TILE + p;

        /* ---- stencil from staged smem [r][c][px]; Y -> bf16 swizzled ---- */
        float xf[16];
        {
            float dxf[16], dyf[16];
            #pragma unroll
            for (int j = 0; j < 16; ++j) {
                int c = chb + j;
                const float* b0 = XSf + (0*32 + c) * XSR + p + 3;
                const float* b1 = XSf + (1*32 + c) * XSR + p + 3;
                const float* b2 = XSf + (2*32 + c) * XSR + p + 3;
                float ul = b0[0], uc = b0[1], ur = b0[2];
                float cl = b1[0], cc = b1[1], cr = b1[2];
                float bl = b2[0], bc = b2[1], br = b2[2];
                xf[j]  = cc;
                dxf[j] = 0.125f * ((bl - ul) + 2.f * (bc - uc) + (br - ur));
                dyf[j] = 0.125f * ((ur - ul) + 2.f * (cr - cl) + (br - bl));
            }
            const uint32_t psw = (uint32_t)((p & 7) << 4);
            char* yrow = smb + Y_B + p * 256;
            #pragma unroll
            for (int q = 0; q < 2; ++q) {
                uint4 vx, vdx, vdy;
                vx.x  = pkbf(xf [8*q+1], xf [8*q+0]); vx.y  = pkbf(xf [8*q+3], xf [8*q+2]);
                vx.z  = pkbf(xf [8*q+5], xf [8*q+4]); vx.w  = pkbf(xf [8*q+7], xf [8*q+6]);
                vdx.x = pkbf(dxf[8*q+1], dxf[8*q+0]); vdx.y = pkbf(dxf[8*q+3], dxf[8*q+2]);
                vdx.z = pkbf(dxf[8*q+5], dxf[8*q+4]); vdx.w = pkbf(dxf[8*q+7], dxf[8*q+6]);
                vdy.x = pkbf(dyf[8*q+1], dyf[8*q+0]); vdy.y = pkbf(dyf[8*q+3], dyf[8*q+2]);
                vdy.z = pkbf(dyf[8*q+5], dyf[8*q+4]); vdy.w = pkbf(dyf[8*q+7], dyf[8*q+6]);
                uint32_t cb = (uint32_t)(chb*2 + q*16);
                *(uint4*)(yrow + ((  0 + cb) ^ psw)) = vx;
                *(uint4*)(yrow + (( 64 + cb) ^ psw)) = vdx;
                *(uint4*)(yrow + ((128 + cb) ^ psw)) = vdy;
            }
        }
        __syncthreads();                       /* (1) Y visible; XS reads done */

        /* ---- stage NEXT tile (overlaps the GEMMs below) ---- */
        {
            int nt = tile + gridDim.x;
            if (nt < NTILES) stage_tile(xin, su, nt, tid);
            else CP_COMMIT();
        }

        /* ---- GEMM1: H[128x256] = Y[128x96] x W0^T ; warp = (mg, ng) ---- */
        {
            float acc[4][8][4];
            #pragma unroll
            for (int rb = 0; rb < 4; ++rb)
                #pragma unroll
                for (int nl = 0; nl < 8; ++nl)
                    #pragma unroll
                    for (int q = 0; q < 4; ++q) acc[rb][nl][q] = 0.f;

            const uint32_t arow = (uint32_t)(mg*64 + (lane & 15));
            const uint32_t abase = su + Y_B + arow * 256;
            const uint32_t asw = (uint32_t)(((lane >> 4) * 16) ^ ((arow & 7) << 4));

            #pragma unroll
            for (int kt = 0; kt < 6; ++kt) {
                uint32_t a[4][4];
                #pragma unroll
                for (int rb = 0; rb < 4; ++rb)
                    ldsm4(a[rb][0], a[rb][1], a[rb][2], a[rb][3],
                          abase + rb*16*256 + ((uint32_t)(kt*32) ^ asw));
                const uint2* bf = w0f + (kt*32 + ng*8)*32 + lane;
                #pragma unroll
                for (int nl = 0; nl < 8; ++nl) {
                    uint2 b = bf[nl*32];
                    #pragma unroll
                    for (int rb = 0; rb < 4; ++rb)
                        mma16(acc[rb][nl][0], acc[rb][nl][1], acc[rb][nl][2], acc[rb][nl][3],
                              a[rb][0], a[rb][1], a[rb][2], a[rb][3], b.x, b.y);
                }
            }
            char* hb = smb + H_B;
            #pragma unroll
            for (int rb = 0; rb < 4; ++rb) {
                int r0 = mg*64 + rb*16 + g;
                #pragma unroll
                for (int nl = 0; nl < 8; ++nl) {
                    uint32_t cb = (uint32_t)(((ng*8 + nl)*16 + 4*tig) ^ (g << 4));
                    *(uint32_t*)(hb + r0*512 + cb)     = pkbf(acc[rb][nl][1], acc[rb][nl][0]);
                    *(uint32_t*)(hb + (r0+8)*512 + cb) = pkbf(acc[rb][nl][3], acc[rb][nl][2]);
                }
            }
        }
        __syncthreads();                       /* (2) H visible */

        /* ---- GEMM2: D[128x32] = H x W1^T ; warp owns rows rw2..rw2+15 ---- */
        {
            float dacc[4][4];
            #pragma unroll
            for (int nt = 0; nt < 4; ++nt)
                #pragma unroll
                for (int q = 0; q < 4; ++q) dacc[nt][q] = 0.f;

            const uint32_t arow = (uint32_t)(rw2 + (lane & 15));
            const uint32_t abase = su + H_B + arow * 512;
            const uint32_t asw = (uint32_t)(((lane >> 4) * 16) ^ ((arow & 7) << 4));

            #pragma unroll
            for (int kt = 0; kt < 16; ++kt) {
                uint32_t a0, a1, a2, a3;
                ldsm4(a0, a1, a2, a3, abase + ((uint32_t)(kt*32) ^ asw));
                const uint2* bf = w1f + (kt*4)*32 + lane;
                #pragma unroll
                for (int nt = 0; nt < 4; ++nt) {
                    uint2 b = bf[nt*32];
                    mma16(dacc[nt][0], dacc[nt][1], dacc[nt][2], dacc[nt][3],
                          a0, a1, a2, a3, b.x, b.y);
                }
            }
            #pragma unroll
            for (int nt = 0; nt < 4; ++nt) {
                *(float2*)&Dsm[(rw2+g)*36   + nt*8 + 2*tig] = make_float2(dacc[nt][0], dacc[nt][1]);
                *(float2*)&Dsm[(rw2+g+8)*36 + nt*8 + 2*tig] = make_float2(dacc[nt][2], dacc[nt][3]);
            }
        }
        __syncthreads();                       /* (3) D visible; H free */

        /* ---- epilogue: mask, sigmoid, store ---- */
        uint2 rb2 = threefry(fk.x, fk.y, 0u, (uint32_t)pg);
        uint32_t bits = rb2.x ^ rb2.y;
        float u = __uint_as_float((bits >> 9) | 0x3f800000u) - 1.0f;
        float m = (u > 0.5f) ? 1.0f : 0.0f;

        float outv[16];
        #pragma unroll
        for (int q = 0; q < 4; ++q) {
            float4 dv = *(const float4*)&Dsm[p*36 + chb + 4*q];
            float dd[4] = {dv.x, dv.y, dv.z, dv.w};
            #pragma unroll
            for (int e = 0; e < 4; ++e) {
                int c = chb + 4*q + e;
                float xx = xf[4*q + e];
                float d = dd[e] + c2[c];
                float t = xx + d * m;
                float sg = __fdividef(1.0f, 1.0f + __expf(-t));
                outv[4*q + e] = (c < 3) ? xx : sg;
            }
        }
        if (OUTMODE == 0) {
            #pragma unroll
            for (int j = 0; j < 16; ++j)
                xout[(size_t)(chb + j) * NPIX + pg] = outv[j];
        } else {
            /* stage AoS output in H slab (swizzled), then coalesced STG.128 */
            float* os = (float*)(smb + H_B);
            const uint32_t px4 = (uint32_t)((p & 7) << 2);
            #pragma unroll
            for (int q = 0; q < 4; ++q)
                *(float4*)(os + p*32 + (((uint32_t)(chb + 4*q)) ^ px4)) =
                    make_float4(outv[4*q], outv[4*q+1], outv[4*q+2], outv[4*q+3]);
            __syncthreads();
            float4* dst = (float4*)(xout + (size_t)tile * TILE * CN);
            #pragma unroll
            for (int it = 0; it < 4; ++it) {
                int i = tid + it * THREADS;    /* 0..1023 */
                int pp = i >> 3, gq = i & 7;
                float4 v = *(const float4*)(os + pp*32 + (((uint32_t)(4*gq)) ^ ((uint32_t)((pp & 7) << 2))));
                dst[i] = v;
            }
        }

        CP_WAIT0();
        __syncthreads();                       /* (4) XS(t+1) ready; D reads done */
    }
}

/* ---------------- launch ---------------- */
extern "C" void kernel_launch(void* const* d_in, const int* in_sizes, int n_in,
                              void* d_out, int out_size)
{
    const float* x    = (const float*)d_in[0];
    const float* fc0w = (const float*)d_in[1];
    const float* fc0b = (const float*)d_in[2];
    const float* fc1w = (const float*)d_in[3];
    const int*   st   = (const int*)d_in[4];
    float* out = (float*)d_out;

    float *p0 = nullptr, *p1 = nullptr;
    cudaGetSymbolAddress((void**)&p0, g_p0);
    cudaGetSymbolAddress((void**)&p1, g_p1);

    int nsm = 148;
    cudaDeviceGetAttribute(&nsm, cudaDevAttrMultiProcessorCount, 0);

    cudaFuncSetAttribute((const void*)nca_mma<0>,
                         cudaFuncAttributeMaxDynamicSharedMemorySize, SMEM_BYTES);
    cudaFuncSetAttribute((const void*)nca_mma<1>,
                         cudaFuncAttributeMaxDynamicSharedMemorySize, SMEM_BYTES);

    pad_kernel<<<1, 32>>>();
    aos_to_planar<<<NPIX / 32, 256>>>(x, p0);
    nca_mma<0><<<nsm, THREADS, SMEM_BYTES>>>(p0, p1,  fc0w, fc0b, fc1w, st, 0);
    nca_mma<1><<<nsm, THREADS, SMEM_BYTES>>>(p1, out, fc0w, fc0b, fc1w, st, 1);
}

// round 11
// speedup vs baseline: 6.5139x; 1.4545x over previous
#include <cuda_runtime.h>
#include <cstdint>

#define CN   32
#define HID  256
#define K3   96
#define WW   256
#define NPIX (8*256*256)         /* 524288 */
#define TILE 128
#define NTILES (NPIX/TILE)       /* 4096 */
#define THREADS 256

/* smem byte offsets */
#define W0F_B 0                  /* 6kt*32nt*32lane*8B  = 49152 */
#define W1F_B 49152              /* 16kt*4nt*32lane*8B  = 16384 */
#define Y_B   65536              /* 128 rows * 256 B (bf16, swizzled); per-warp D aliases */
#define X_B   98304              /* 128*36 f32 = 18432 */
#define XS0_B 116736             /* staged window: 96 pairs * 144 words * 4 = 55296 B */
#define XS1_B 172032
#define C2_B  227328             /* 32 f32 */
#define SMEM_BYTES 227456

#define XST   36                 /* X/D row stride (words): %4==0, %32==4 */
#define XSROW 144                /* XS pair-row stride (words): skewed rows fit (max word 140) */

/* planar (SoA) ping-pong scratch: [c][pix] */
__device__ float g_p0[(size_t)CN * NPIX];
__device__ float g_p1[(size_t)CN * NPIX];

/* ================= helpers ================= */
static __device__ __forceinline__ uint32_t smem_u32(const void* p) {
    uint32_t a;
    asm("{ .reg .u64 t; cvta.to.shared.u64 t, %1; cvt.u32.u64 %0, t; }" : "=r"(a) : "l"(p));
    return a;
}
static __device__ __forceinline__ uint32_t pkbf(float hi, float lo) {
    uint32_t r;
    asm("cvt.rn.bf16x2.f32 %0, %1, %2;" : "=r"(r) : "f"(hi), "f"(lo));
    return r;
}
static __device__ __forceinline__ void ldsm4(uint32_t& r0, uint32_t& r1,
                                             uint32_t& r2, uint32_t& r3, uint32_t addr) {
    asm volatile("ldmatrix.sync.aligned.m8n8.x4.shared.b16 {%0,%1,%2,%3}, [%4];"
                 : "=r"(r0), "=r"(r1), "=r"(r2), "=r"(r3) : "r"(addr));
}
static __device__ __forceinline__ void mma16(float& d0, float& d1, float& d2, float& d3,
                                             uint32_t a0, uint32_t a1, uint32_t a2, uint32_t a3,
                                             uint32_t b0, uint32_t b1) {
    asm volatile("mma.sync.aligned.m16n8k16.row.col.f32.bf16.bf16.f32 "
                 "{%0,%1,%2,%3}, {%4,%5,%6,%7}, {%8,%9}, {%0,%1,%2,%3};"
                 : "+f"(d0), "+f"(d1), "+f"(d2), "+f"(d3)
                 : "r"(a0), "r"(a1), "r"(a2), "r"(a3), "r"(b0), "r"(b1));
}
static __device__ __forceinline__ void cp4(uint32_t saddr, const float* g, bool inb) {
    int sz = inb ? 4 : 0;
    asm volatile("cp.async.ca.shared.global [%0], [%1], 4, %2;"
                 :: "r"(saddr), "l"(g), "r"(sz) : "memory");
}
static __device__ __forceinline__ void cp16(uint32_t saddr, const float* g, bool inb) {
    int sz = inb ? 16 : 0;
    asm volatile("cp.async.cg.shared.global [%0], [%1], 16, %2;"
                 :: "r"(saddr), "l"(g), "r"(sz) : "memory");
}
#define CP_COMMIT() asm volatile("cp.async.commit_group;" ::: "memory")
#define CP_WAIT0()  asm volatile("cp.async.wait_group 0;" ::: "memory")

/* ---------------- JAX threefry2x32 (validated R2) ---------------- */
static __device__ __forceinline__ uint2 threefry(uint32_t k0, uint32_t k1,
                                                 uint32_t x0, uint32_t x1) {
    uint32_t ks2 = k0 ^ k1 ^ 0x1BD11BDAu;
    x0 += k0; x1 += k1;
#define TF_R(r) { x0 += x1; x1 = __funnelshift_l(x1, x1, (r)); x1 ^= x0; }
    TF_R(13) TF_R(15) TF_R(26) TF_R(6)   x0 += k1;  x1 += ks2 + 1u;
    TF_R(17) TF_R(29) TF_R(16) TF_R(24)  x0 += ks2; x1 += k0  + 2u;
    TF_R(13) TF_R(15) TF_R(26) TF_R(6)   x0 += k0;  x1 += k1  + 3u;
    TF_R(17) TF_R(29) TF_R(16) TF_R(24)  x0 += k1;  x1 += ks2 + 4u;
    TF_R(13) TF_R(15) TF_R(26) TF_R(6)   x0 += ks2; x1 += k0  + 5u;
#undef TF_R
    return make_uint2(x0, x1);
}

/* pad kernel: shifts ncu launch index so -s 5 lands on a step kernel */
__global__ void pad_kernel() {}

/* ---------------- AoS [pix][32] -> planar [c][pix] ---------------- */
__global__ void __launch_bounds__(256, 4)
aos_to_planar(const float* __restrict__ src, float* __restrict__ dst)
{
    __shared__ float tile[CN][33];
    const int tid = threadIdx.x;
    const int base = blockIdx.x * 32;
    {
        const int p  = tid >> 3;
        const int cg = tid & 7;
        float4 v = *(const float4*)(src + ((size_t)(base + p)) * CN + cg * 4);
        tile[cg*4 + 0][p] = v.x;  tile[cg*4 + 1][p] = v.y;
        tile[cg*4 + 2][p] = v.z;  tile[cg*4 + 3][p] = v.w;
    }
    __syncthreads();
    {
        const int p = tid & 31;
        const int c0 = tid >> 5;
        #pragma unroll
        for (int i = 0; i < 4; ++i) {
            const int c = c0 + i * 8;
            dst[(size_t)c * NPIX + base + p] = tile[c][p];
        }
    }
}

/* stage tile T's stencil window [r][c][px] (coalesced, +8-word skew on c>=16) */
static __device__ __forceinline__ void stage_tile(const float* __restrict__ xin,
                                                  uint32_t su, uint32_t xsoff,
                                                  int T, int tid)
{
    const int pgb = T * TILE;
    const int rowg = pgb >> 8;
    const int h = rowg & 255;
    const int wb = pgb & 255;
    #pragma unroll
    for (int it = 0; it < 12; ++it) {
        int u = tid + it * THREADS;       /* 0..3071 */
        int pair = u >> 5;
        int k    = u & 31;
        int r = pair >> 5, c = pair & 31;
        int skew = (c >> 4) << 3;
        int ri = h + r - 1;
        bool inb = (ri >= 0) && (ri < 256);
        const float* g = inb ? (xin + (size_t)c * NPIX + (((size_t)(rowg + r - 1)) << 8) + wb + 4*k)
                             : xin;
        uint32_t sa = su + xsoff + (uint32_t)((pair * XSROW + skew + 4 + 4*k) << 2);
        cp16(sa, g, inb);
    }
    if (tid < 192) {
        int pair = tid >> 1, side = tid & 1;
        int r = pair >> 5, c = pair & 31;
        int skew = (c >> 4) << 3;
        int ri = h + r - 1;
        int wcoord = side ? (wb + 128) : (wb - 1);
        bool inb = (ri >= 0) && (ri < 256) && (wcoord >= 0) && (wcoord < 256);
        const float* g = inb ? (xin + (size_t)c * NPIX + (((size_t)(rowg + r - 1)) << 8) + wcoord)
                             : xin;
        uint32_t sa = su + xsoff + (uint32_t)((pair * XSROW + skew + (side ? 132 : 3)) << 2);
        cp4(sa, g, inb);
    }
    CP_COMMIT();
}

/* ================= fused NCA step: warp-local tiles, register-H ================= */
template <int OUTMODE>   /* 0 = planar out, 1 = AoS out (final) */
__global__ void __launch_bounds__(THREADS, 1)
nca_mma(const float* __restrict__ xin, float* __restrict__ xout,
        const float* __restrict__ fc0w, const float* __restrict__ fc0b,
        const float* __restrict__ fc1w, const int* __restrict__ stepsPtr,
        int stepIdx)
{
    extern __shared__ char smb[];
    const uint32_t su = smem_u32(smb);
    const int tid  = threadIdx.x;
    const int lane = tid & 31;
    const int warp = tid >> 5;
    const int rw   = warp * 16;           /* warp's pixel-row base */
    const int pxi  = lane & 15;           /* pixel within warp     */
    const int chh  = lane >> 4;           /* channel half 0/1      */
    const int chb  = chh * 16;
    const int S = *stepsPtr;

    if (stepIdx >= S) {                   /* identity pass-through */
        const int p = tid & 127;
        const int cb = (tid >> 7) * 16;
        for (int tile = blockIdx.x; tile < NTILES; tile += gridDim.x) {
            const int pg = tile * TILE + p;
            #pragma unroll
            for (int j = 0; j < 16; ++j) {
                int c = cb + j;
                float v = xin[(size_t)c * NPIX + pg];
                if (OUTMODE == 0) xout[(size_t)c * NPIX + pg] = v;
                else              xout[(size_t)pg * CN + c] = v;
            }
        }
        return;
    }

    /* -------- one-time: weight fragments (bf16) + bias fold -------- */
    uint2* w0f = (uint2*)(smb + W0F_B);
    for (int e = tid; e < 6*32*32; e += THREADS) {
        int kt = e >> 10, rem = e & 1023, nt = rem >> 5, t = rem & 31;
        int gg = t >> 2, tg = t & 3;
        int n = nt*8 + gg, k = kt*16 + 2*tg;
        uint2 v;
        v.x = pkbf(fc0w[n*K3 + k + 1], fc0w[n*K3 + k]);
        v.y = pkbf(fc0w[n*K3 + k + 9], fc0w[n*K3 + k + 8]);
        w0f[e] = v;
    }
    uint2* w1f = (uint2*)(smb + W1F_B);
    for (int e = tid; e < 16*4*32; e += THREADS) {
        int kt = e >> 7, rem = e & 127, nt = rem >> 5, t = rem & 31;
        int gg = t >> 2, tg = t & 3;
        int n = nt*8 + gg, k = kt*16 + 2*tg;
        uint2 v;
        v.x = pkbf(fc1w[n*HID + k + 1], fc1w[n*HID + k]);
        v.y = pkbf(fc1w[n*HID + k + 9], fc1w[n*HID + k + 8]);
        w1f[e] = v;
    }
    float* c2 = (float*)(smb + C2_B);
    if (tid < CN) {                        /* c2 = W1 * b */
        float s = 0.f;
        const float* wr = fc1w + tid * HID;
        #pragma unroll 8
        for (int h2 = 0; h2 < HID; ++h2) s += wr[h2] * fc0b[h2];
        c2[tid] = s;
    }
    __syncthreads();

    float* Xsm = (float*)(smb + X_B);
    float* Dw  = (float*)(smb + Y_B + rw * 256);   /* warp-local D, aliases own Y rows */

    const uint2 fk = threefry(0u, 42u, 0u, (uint32_t)stepIdx);
    const int g = lane >> 2, tig = lane & 3;

    /* prologue: stage first tile into buffer 0 */
    int buf = 0;
    if (blockIdx.x < NTILES) stage_tile(xin, su, XS0_B, blockIdx.x, tid);

    for (int tile = blockIdx.x; tile < NTILES; tile += gridDim.x) {
        CP_WAIT0();
        __syncthreads();                  /* XS[buf] published to all warps */

        const float* XSf = (const float*)(smb + (buf ? XS1_B : XS0_B));
        const int pl = rw + pxi;          /* pixel within tile */
        const int pg = tile * TILE + pl;

        /* ---- stencil (own pixel, 16 channels): Y(own rows) + X ---- */
        {
            float xf[16], dxf[16], dyf[16];
            const int skew = chh << 3;
            #pragma unroll
            for (int j = 0; j < 16; ++j) {
                int c = chb + j;
                const float* b0 = XSf + (0*32 + c)*XSROW + skew + pl + 3;
                const float* b1 = XSf + (1*32 + c)*XSROW + skew + pl + 3;
                const float* b2 = XSf + (2*32 + c)*XSROW + skew + pl + 3;
                float ul = b0[0], uc = b0[1], ur = b0[2];
                float cl = b1[0], cc = b1[1], cr = b1[2];
                float bl = b2[0], bc = b2[1], br = b2[2];
                xf[j]  = cc;
                dxf[j] = 0.125f * ((bl - ul) + 2.f * (bc - uc) + (br - ur));
                dyf[j] = 0.125f * ((ur - ul) + 2.f * (cr - cl) + (br - bl));
            }
            const uint32_t psw = (uint32_t)((pl & 7) << 4);
            char* yrow = smb + Y_B + pl * 256;
            #pragma unroll
            for (int q = 0; q < 2; ++q) {
                uint4 vx, vdx, vdy;
                vx.x  = pkbf(xf [8*q+1], xf [8*q+0]); vx.y  = pkbf(xf [8*q+3], xf [8*q+2]);
                vx.z  = pkbf(xf [8*q+5], xf [8*q+4]); vx.w  = pkbf(xf [8*q+7], xf [8*q+6]);
                vdx.x = pkbf(dxf[8*q+1], dxf[8*q+0]); vdx.y = pkbf(dxf[8*q+3], dxf[8*q+2]);
                vdx.z = pkbf(dxf[8*q+5], dxf[8*q+4]); vdx.w = pkbf(dxf[8*q+7], dxf[8*q+6]);
                vdy.x = pkbf(dyf[8*q+1], dyf[8*q+0]); vdy.y = pkbf(dyf[8*q+3], dyf[8*q+2]);
                vdy.z = pkbf(dyf[8*q+5], dyf[8*q+4]); vdy.w = pkbf(dyf[8*q+7], dyf[8*q+6]);
                uint32_t cb = (uint32_t)(chb*2 + q*16);
                *(uint4*)(yrow + ((  0 + cb) ^ psw)) = vx;
                *(uint4*)(yrow + (( 64 + cb) ^ psw)) = vdx;
                *(uint4*)(yrow + ((128 + cb) ^ psw)) = vdy;
            }
            #pragma unroll
            for (int q = 0; q < 4; ++q)
                *(float4*)&Xsm[pl*XST + chb + 4*q] =
                    make_float4(xf[4*q], xf[4*q+1], xf[4*q+2], xf[4*q+3]);
        }

        /* ---- stage NEXT tile into other buffer (overlaps GEMMs) ---- */
        {
            int nt = tile + gridDim.x;
            if (nt < NTILES) stage_tile(xin, su, buf ? XS0_B : XS1_B, nt, tid);
            else CP_COMMIT();
        }
        __syncwarp();                     /* own Y rows visible to own ldsm */

        /* ---- GEMM1: H[16 x 256] in registers; A = own Y rows ---- */
        float acc[32][4];
        #pragma unroll
        for (int nt = 0; nt < 32; ++nt)
            #pragma unroll
            for (int q = 0; q < 4; ++q) acc[nt][q] = 0.f;
        {
            const uint32_t abase = su + Y_B + (uint32_t)pl * 256;
            const uint32_t asw = ((uint32_t)chh * 16) ^ (((uint32_t)(pxi & 7)) << 4);
            #pragma unroll
            for (int kt = 0; kt < 6; ++kt) {
                uint32_t a0, a1, a2, a3;
                ldsm4(a0, a1, a2, a3, abase + (((uint32_t)(kt*32)) ^ asw));
                const uint2* bf = w0f + kt*32*32 + lane;
                #pragma unroll
                for (int nt = 0; nt < 32; ++nt) {
                    uint2 b = bf[nt*32];
                    mma16(acc[nt][0], acc[nt][1], acc[nt][2], acc[nt][3],
                          a0, a1, a2, a3, b.x, b.y);
                }
            }
        }

        /* ---- GEMM2: D[16 x 32]; A built from acc registers ---- */
        float dacc[4][4];
        #pragma unroll
        for (int nt = 0; nt < 4; ++nt)
            #pragma unroll
            for (int q = 0; q < 4; ++q) dacc[nt][q] = 0.f;
        #pragma unroll
        for (int j = 0; j < 16; ++j) {
            uint32_t a0 = pkbf(acc[2*j  ][1], acc[2*j  ][0]);
            uint32_t a1 = pkbf(acc[2*j  ][3], acc[2*j  ][2]);
            uint32_t a2 = pkbf(acc[2*j+1][1], acc[2*j+1][0]);
            uint32_t a3 = pkbf(acc[2*j+1][3], acc[2*j+1][2]);
            const uint2* bf = w1f + j*4*32 + lane;
            #pragma unroll
            for (int nt = 0; nt < 4; ++nt) {
                uint2 b = bf[nt*32];
                mma16(dacc[nt][0], dacc[nt][1], dacc[nt][2], dacc[nt][3],
                      a0, a1, a2, a3, b.x, b.y);
            }
        }

        /* ---- D -> warp-local smem (aliases own dead Y rows) ---- */
        #pragma unroll
        for (int nt = 0; nt < 4; ++nt) {
            *(float2*)&Dw[g*XST     + nt*8 + 2*tig] = make_float2(dacc[nt][0], dacc[nt][1]);
            *(float2*)&Dw[(g+8)*XST + nt*8 + 2*tig] = make_float2(dacc[nt][2], dacc[nt][3]);
        }
        __syncwarp();

        /* ---- epilogue: mask, sigmoid, store (warp-local) ---- */
        uint2 rb2 = threefry(fk.x, fk.y, 0u, (uint32_t)pg);
        uint32_t bits = rb2.x ^ rb2.y;
        float u = __uint_as_float((bits >> 9) | 0x3f800000u) - 1.0f;
        float m = (u > 0.5f) ? 1.0f : 0.0f;

        float outv[16];
        #pragma unroll
        for (int q = 0; q < 4; ++q) {
            float4 dv = *(const float4*)&Dw[pxi*XST + chb + 4*q];
            float4 xv = *(const float4*)&Xsm[pl*XST + chb + 4*q];
            float dd[4] = {dv.x, dv.y, dv.z, dv.w};
            float xx[4] = {xv.x, xv.y, xv.z, xv.w};
            #pragma unroll
            for (int e = 0; e < 4; ++e) {
                int c = chb + 4*q + e;
                float d = dd[e] + c2[c];
                float t = xx[e] + d * m;
                float sg = __fdividef(1.0f, 1.0f + __expf(-t));
                outv[4*q + e] = (c < 3) ? xx[e] : sg;
            }
        }
        if (OUTMODE == 0) {
            #pragma unroll
            for (int j = 0; j < 16; ++j)
                xout[(size_t)(chb + j) * NPIX + pg] = outv[j];
        } else {
            float* dst = xout + (size_t)pg * CN + chb;
            #pragma unroll
            for (int q = 0; q < 4; ++q)
                *(float4*)(dst + 4*q) = make_float4(outv[4*q], outv[4*q+1],
                                                    outv[4*q+2], outv[4*q+3]);
        }
        buf ^= 1;
    }
}

/* ---------------- launch ---------------- */
extern "C" void kernel_launch(void* const* d_in, const int* in_sizes, int n_in,
                              void* d_out, int out_size)
{
    const float* x    = (const float*)d_in[0];
    const float* fc0w = (const float*)d_in[1];
    const float* fc0b = (const float*)d_in[2];
    const float* fc1w = (const float*)d_in[3];
    const int*   st   = (const int*)d_in[4];
    float* out = (float*)d_out;

    float *p0 = nullptr, *p1 = nullptr;
    cudaGetSymbolAddress((void**)&p0, g_p0);
    cudaGetSymbolAddress((void**)&p1, g_p1);

    int nsm = 148;
    cudaDeviceGetAttribute(&nsm, cudaDevAttrMultiProcessorCount, 0);

    cudaFuncSetAttribute((const void*)nca_mma<0>,
                         cudaFuncAttributeMaxDynamicSharedMemorySize, SMEM_BYTES);
    cudaFuncSetAttribute((const void*)nca_mma<1>,
                         cudaFuncAttributeMaxDynamicSharedMemorySize, SMEM_BYTES);

    pad_kernel<<<1, 32>>>();
    aos_to_planar<<<NPIX / 32, 256>>>(x, p0);
    nca_mma<0><<<nsm, THREADS, SMEM_BYTES>>>(p0, p1,  fc0w, fc0b, fc1w, st, 0);
    nca_mma<1><<<nsm, THREADS, SMEM_BYTES>>>(p1, out, fc0w, fc0b, fc1w, st, 1);
}